// round 10
// baseline (speedup 1.0000x reference)
#include <cuda_runtime.h>
#include <cuda_bf16.h>
#include <cstdint>
#include <math.h>

#define NV   100000
#define ME   50000
#define NNZE 800000
#define HD   128
#define NCLS 40
#define DEPTH 4

typedef unsigned long long u64;

// -------- scratch (no allocations allowed; __device__ globals) --------
__device__ float g_h [NV * HD];     // current features x
__device__ float g_h0[NV * HD];     // x0 (post first relu)
__device__ float g_Xe[ME * HD];     // edge features
// weights pre-split to bf16 hi/lo in MMA fragment layout. slot0=W0, 1..4=folded
__device__ __align__(16) __nv_bfloat16 g_Bhi[5 * HD * HD];
__device__ __align__(16) __nv_bfloat16 g_Blo[5 * HD * HD];
__device__ int g_cnt_e[ME], g_cnt_v[NV];
__device__ int g_off_e[ME + 1], g_off_v[NV + 1];
__device__ int g_cur_e[ME], g_cur_v[NV];
__device__ int g_adj_e[NNZE];   // vertex ids grouped by edge
__device__ int g_adj_v[NNZE];   // edge ids grouped by vertex

// -------- f32x2 helpers (used by gemm_out) -----------------------------
__device__ __forceinline__ void ffma2(u64& d, u64 a, u64 b, u64 c) {
    asm("fma.rn.f32x2 %0, %1, %2, %3;" : "=l"(d) : "l"(a), "l"(b), "l"(c));
}
__device__ __forceinline__ u64 bcast2(float a) {
    u64 r;
    asm("mov.b64 %0, {%1, %1};" : "=l"(r) : "f"(a));
    return r;
}
__device__ __forceinline__ float2 unpack2(u64 u) {
    float2 f;
    asm("mov.b64 {%0, %1}, %2;" : "=f"(f.x), "=f"(f.y) : "l"(u));
    return f;
}

// -------- bf16 split helpers -------------------------------------------
__device__ __forceinline__ void bsplit(float a, __nv_bfloat16& hi, __nv_bfloat16& lo) {
    hi = __float2bfloat16_rn(a);
    lo = __float2bfloat16_rn(a - __bfloat162float(hi));
}
__device__ __forceinline__ uint32_t packbf(__nv_bfloat16 a, __nv_bfloat16 b) {
    __nv_bfloat162 p;
    p.x = a; p.y = b;
    return *(uint32_t*)&p;
}

// mma.sync m16n8k16 bf16 -> f32 accum (baseline PTX, no arch suffix)
__device__ __forceinline__ void mma16816(float* d, const uint4& a, const uint2& b) {
    asm volatile(
        "mma.sync.aligned.m16n8k16.row.col.f32.bf16.bf16.f32 "
        "{%0,%1,%2,%3}, {%4,%5,%6,%7}, {%8,%9}, {%0,%1,%2,%3};"
        : "+f"(d[0]), "+f"(d[1]), "+f"(d[2]), "+f"(d[3])
        : "r"(a.x), "r"(a.y), "r"(a.z), "r"(a.w), "r"(b.x), "r"(b.y));
}

// ---------------------------------------------------------------------
__global__ void k_zero_counts() {
    int i = blockIdx.x * blockDim.x + threadIdx.x;
    if (i < ME) g_cnt_e[i] = 0;
    if (i < NV) g_cnt_v[i] = 0;
}

__global__ void k_count(const int* __restrict__ vtx, const int* __restrict__ edg) {
    int i = blockIdx.x * blockDim.x + threadIdx.x;
    if (i >= NNZE) return;
    atomicAdd(&g_cnt_e[edg[i]], 1);
    atomicAdd(&g_cnt_v[vtx[i]], 1);
}

__global__ void k_scan() {
    const int which = blockIdx.x;
    const int len = which ? NV : ME;
    const int* cnt = which ? g_cnt_v : g_cnt_e;
    int* off = which ? g_off_v : g_off_e;
    int* cur = which ? g_cur_v : g_cur_e;

    __shared__ int sm[1024];
    int t = threadIdx.x;
    int chunk = (len + 1023) >> 10;
    int lo = t * chunk;
    int hi = min(lo + chunk, len);

    int s = 0;
    for (int i = lo; i < hi; i++) s += cnt[i];
    sm[t] = s;
    __syncthreads();
    for (int o = 1; o < 1024; o <<= 1) {
        int add = (t >= o) ? sm[t - o] : 0;
        __syncthreads();
        sm[t] += add;
        __syncthreads();
    }
    int excl = sm[t] - s;
    int run = excl;
    for (int i = lo; i < hi; i++) {
        off[i] = run;
        cur[i] = run;
        run += cnt[i];
    }
    if (t == 1023) off[len] = run;
}

__global__ void k_fill(const int* __restrict__ vtx, const int* __restrict__ edg) {
    int i = blockIdx.x * blockDim.x + threadIdx.x;
    if (i >= NNZE) return;
    int e = edg[i], v = vtx[i];
    int pe = atomicAdd(&g_cur_e[e], 1);
    g_adj_e[pe] = v;
    int pv = atomicAdd(&g_cur_v[v], 1);
    g_adj_v[pv] = e;
}

// -------- weight prep (all 5 slots in one launch, grid.y = slot) --------
// B frag (m16n8k16 col operand): (k,n) of 16x8 tile ->
//   lane=(n&7)*4+((k&7)>>1), elem=((kt*16+nt)*32+lane)*4 + ((k>>3)&1)*2 + (k&1)
__global__ void k_prep_frag(const float* __restrict__ W0, const float* __restrict__ Ws) {
    int slot = blockIdx.y;
    int idx = blockIdx.x * blockDim.x + threadIdx.x;
    if (idx >= HD * HD) return;
    const float* W = (slot == 0) ? W0 : Ws + (slot - 1) * HD * HD;
    int k = idx >> 7, n = idx & 127;
    float w = W[idx];
    if (slot > 0) {
        float beta = logf(0.5f / (float)slot + 1.0f);
        w = beta * w;
        if (k == n) w += (1.0f - beta);
    }
    __nv_bfloat16 hi, lo;
    bsplit(w, hi, lo);
    int kt = k >> 4, kc = k & 15;
    int nt = n >> 3, nc = n & 7;
    int lane = nc * 4 + ((kc & 7) >> 1);
    int elem = ((kt * 16 + nt) * 32 + lane) * 4 + ((kc >> 3) << 1) + (kc & 1);
    g_Bhi[slot * HD * HD + elem] = hi;
    g_Blo[slot * HD * HD + elem] = lo;
}

// -------- edge aggregation: warp per edge, gather-only, MLP-8 -----------
__global__ __launch_bounds__(256) void k_edge_agg() {
    int e = (blockIdx.x * blockDim.x + threadIdx.x) >> 5;
    if (e >= ME) return;
    int lane = threadIdx.x & 31;
    int beg = g_off_e[e], end = g_off_e[e + 1];
    float4 acc = make_float4(0.f, 0.f, 0.f, 0.f);
    int p = beg;
    for (; p + 8 <= end; p += 8) {
        int v0 = g_adj_e[p],     v1 = g_adj_e[p + 1];
        int v2 = g_adj_e[p + 2], v3 = g_adj_e[p + 3];
        int v4 = g_adj_e[p + 4], v5 = g_adj_e[p + 5];
        int v6 = g_adj_e[p + 6], v7 = g_adj_e[p + 7];
        float4 a = *(const float4*)&g_h[v0 * HD + lane * 4];
        float4 b = *(const float4*)&g_h[v1 * HD + lane * 4];
        float4 c = *(const float4*)&g_h[v2 * HD + lane * 4];
        float4 d = *(const float4*)&g_h[v3 * HD + lane * 4];
        float4 ee = *(const float4*)&g_h[v4 * HD + lane * 4];
        float4 f = *(const float4*)&g_h[v5 * HD + lane * 4];
        float4 g = *(const float4*)&g_h[v6 * HD + lane * 4];
        float4 hh = *(const float4*)&g_h[v7 * HD + lane * 4];
        acc.x += (a.x + b.x) + (c.x + d.x) + (ee.x + f.x) + (g.x + hh.x);
        acc.y += (a.y + b.y) + (c.y + d.y) + (ee.y + f.y) + (g.y + hh.y);
        acc.z += (a.z + b.z) + (c.z + d.z) + (ee.z + f.z) + (g.z + hh.z);
        acc.w += (a.w + b.w) + (c.w + d.w) + (ee.w + f.w) + (g.w + hh.w);
    }
    for (; p + 4 <= end; p += 4) {
        int v0 = g_adj_e[p], v1 = g_adj_e[p + 1], v2 = g_adj_e[p + 2], v3 = g_adj_e[p + 3];
        float4 a = *(const float4*)&g_h[v0 * HD + lane * 4];
        float4 b = *(const float4*)&g_h[v1 * HD + lane * 4];
        float4 c = *(const float4*)&g_h[v2 * HD + lane * 4];
        float4 d = *(const float4*)&g_h[v3 * HD + lane * 4];
        acc.x += (a.x + b.x) + (c.x + d.x);
        acc.y += (a.y + b.y) + (c.y + d.y);
        acc.z += (a.z + b.z) + (c.z + d.z);
        acc.w += (a.w + b.w) + (c.w + d.w);
    }
    for (; p < end; p++) {
        int v = g_adj_e[p];
        float4 a = *(const float4*)&g_h[v * HD + lane * 4];
        acc.x += a.x; acc.y += a.y; acc.z += a.z; acc.w += a.w;
    }
    float inv = 1.0f / (float)max(end - beg, 1);
    acc.x *= inv; acc.y *= inv; acc.z *= inv; acc.w *= inv;
    *(float4*)&g_Xe[e * HD + lane * 4] = acc;
}

// ---- MMA GEMM shared pieces --------------------------------------------
#define GB_SMEM (4 * 8192 * 4)

// emit one row's 4 floats (cols lane*4..+3) into frag-layout smem hi/lo
__device__ __forceinline__ void emit_row_frag(
    uint32_t* sAhi, uint32_t* sAlo, int m, int lane, float4 o)
{
    int mt = m >> 4, r = m & 15;
    int kl = lane * 4;
    #pragma unroll
    for (int p = 0; p < 2; p++) {
        int k = kl + p * 2;
        int kt = k >> 4, kc = k & 15;
        int flane = (r & 7) * 4 + ((kc & 7) >> 1);
        int reg = (r >> 3) + ((kc >> 3) << 1);
        int w32 = (((kt * 8 + mt) * 32 + flane) << 2) + reg;
        float va = p ? o.z : o.x;
        float vb = p ? o.w : o.y;
        __nv_bfloat16 ha, la, hb, lb;
        bsplit(va, ha, la);
        bsplit(vb, hb, lb);
        sAhi[w32] = packbf(ha, hb);
        sAlo[w32] = packbf(la, lb);
    }
}

__device__ __forceinline__ void gemm_core_and_epilogue(
    uint32_t* dyn, const float* bias, bool hasBias,
    float* C, float* C2, int m0, int Mrows, int tid)
{
    uint32_t* sAhi = dyn;
    uint32_t* sAlo = dyn + 8192;
    uint32_t* sBhi = dyn + 16384;
    uint32_t* sBlo = dyn + 24576;

    int wid = tid >> 5;
    int lane = tid & 31;
    int mwarp = wid & 3;
    int nwarp = wid >> 2;
    int mt0 = mwarp * 2;
    int nt0 = nwarp * 8;

    float acc[2][8][4];
    #pragma unroll
    for (int i = 0; i < 2; i++)
        #pragma unroll
        for (int j = 0; j < 8; j++)
            #pragma unroll
            for (int q = 0; q < 4; q++) acc[i][j][q] = 0.f;

    #pragma unroll 1
    for (int seg = 0; seg < 3; seg++) {
        const uint4* aBuf = (const uint4*)(seg == 1 ? sAlo : sAhi);
        const uint2* bBuf = (const uint2*)(seg == 2 ? sBlo : sBhi);
        #pragma unroll 1
        for (int kt = 0; kt < 8; kt++) {
            uint4 afr[2];
            afr[0] = aBuf[(kt * 8 + mt0) * 32 + lane];
            afr[1] = aBuf[(kt * 8 + mt0 + 1) * 32 + lane];
            uint2 bfr[8];
            #pragma unroll
            for (int j = 0; j < 8; j++)
                bfr[j] = bBuf[(kt * 16 + nt0 + j) * 32 + lane];
            #pragma unroll
            for (int i = 0; i < 2; i++)
                #pragma unroll
                for (int j = 0; j < 8; j++)
                    mma16816(acc[i][j], afr[i], bfr[j]);
        }
    }

    int rbase = m0 + mwarp * 32 + (lane >> 2);
    int cbase = nwarp * 64 + (lane & 3) * 2;
    #pragma unroll
    for (int i = 0; i < 2; i++) {
        #pragma unroll
        for (int j = 0; j < 8; j++) {
            int col = cbase + j * 8;
            float bx = hasBias ? bias[col] : 0.f;
            float by = hasBias ? bias[col + 1] : 0.f;
            int r0 = rbase + i * 16;
            if (r0 < Mrows) {
                float2 v;
                v.x = fmaxf(acc[i][j][0] + bx, 0.f);
                v.y = fmaxf(acc[i][j][1] + by, 0.f);
                *(float2*)&C[r0 * HD + col] = v;
                if (C2) *(float2*)&C2[r0 * HD + col] = v;
            }
            int r1 = rbase + i * 16 + 8;
            if (r1 < Mrows) {
                float2 v;
                v.x = fmaxf(acc[i][j][2] + bx, 0.f);
                v.y = fmaxf(acc[i][j][3] + by, 0.f);
                *(float2*)&C[r1 * HD + col] = v;
                if (C2) *(float2*)&C2[r1 * HD + col] = v;
            }
        }
    }
}

__device__ __forceinline__ void stage_B(uint32_t* dyn, int slot, int tid) {
    const uint4* srcH = (const uint4*)(g_Bhi + slot * HD * HD);
    const uint4* srcL = (const uint4*)(g_Blo + slot * HD * HD);
    uint4* dstH = (uint4*)(dyn + 16384);
    uint4* dstL = (uint4*)(dyn + 24576);
    #pragma unroll
    for (int it = 0; it < 8; it++) {
        dstH[tid + it * 256] = srcH[tid + it * 256];
        dstL[tid + it * 256] = srcL[tid + it * 256];
    }
}

// ---- layer-0 GEMM: h = h0 = relu(x @ W0 + b0), A from gmem -------------
__global__ __launch_bounds__(256, 1) void gemm_mma0(
    const float* __restrict__ A, const float* __restrict__ bias, int Mrows)
{
    extern __shared__ uint32_t dyn[];
    int tid = threadIdx.x;
    int m0 = blockIdx.x * 128;

    stage_B(dyn, 0, tid);
    {
        uint32_t* sAhi = dyn;
        uint32_t* sAlo = dyn + 8192;
        #pragma unroll
        for (int it = 0; it < 32; it++) {
            int idx2 = tid + it * 256;
            int m = idx2 >> 6;
            int k = (idx2 & 63) * 2;
            int gm = min(m0 + m, Mrows - 1);
            float2 a = *(const float2*)&A[gm * HD + k];
            __nv_bfloat16 h0b, l0b, h1b, l1b;
            bsplit(a.x, h0b, l0b);
            bsplit(a.y, h1b, l1b);
            int kt = k >> 4, kc = k & 15;
            int mt = m >> 4, r = m & 15;
            int lane = (r & 7) * 4 + ((kc & 7) >> 1);
            int reg = (r >> 3) + ((kc >> 3) << 1);
            int w32 = (((kt * 8 + mt) * 32 + lane) << 2) + reg;
            sAhi[w32] = packbf(h0b, h1b);
            sAlo[w32] = packbf(l0b, l1b);
        }
    }
    __syncthreads();
    gemm_core_and_epilogue(dyn, bias, true, g_h, g_h0, m0, Mrows, tid);
}

// ---- fused layer GEMM: h = relu( blend(norm(agg_v(Xe)), h0) @ W' ) -----
// A-staging gathers edge features per row, L2-normalizes (cnt_v division
// cancels), alpha-blends with h0, splits to bf16 frags in smem directly.
__global__ __launch_bounds__(256, 1) void gemm_fused(int slot, int Mrows)
{
    extern __shared__ uint32_t dyn[];
    int tid = threadIdx.x;
    int m0 = blockIdx.x * 128;
    int wid = tid >> 5;
    int lane = tid & 31;

    stage_B(dyn, slot, tid);

    // stage A: warp wid owns rows wid*16..+15, processed in pairs for MLP
    uint32_t* sAhi = dyn;
    uint32_t* sAlo = dyn + 8192;
    #pragma unroll 1
    for (int rr = 0; rr < 16; rr += 2) {
        int mA = wid * 16 + rr;
        int mB = mA + 1;
        int vA = min(m0 + mA, Mrows - 1);
        int vB = min(m0 + mB, Mrows - 1);
        int pA = g_off_v[vA], eA = g_off_v[vA + 1];
        int pB = g_off_v[vB], eB = g_off_v[vB + 1];
        float4 accA = make_float4(0.f, 0.f, 0.f, 0.f);
        float4 accB = make_float4(0.f, 0.f, 0.f, 0.f);
        // joint unroll-4 over both rows: up to 8 outstanding gathers
        while (pA + 4 <= eA && pB + 4 <= eB) {
            int a0 = g_adj_v[pA], a1 = g_adj_v[pA + 1], a2 = g_adj_v[pA + 2], a3 = g_adj_v[pA + 3];
            int b0 = g_adj_v[pB], b1 = g_adj_v[pB + 1], b2 = g_adj_v[pB + 2], b3 = g_adj_v[pB + 3];
            float4 xa0 = *(const float4*)&g_Xe[a0 * HD + lane * 4];
            float4 xa1 = *(const float4*)&g_Xe[a1 * HD + lane * 4];
            float4 xa2 = *(const float4*)&g_Xe[a2 * HD + lane * 4];
            float4 xa3 = *(const float4*)&g_Xe[a3 * HD + lane * 4];
            float4 xb0 = *(const float4*)&g_Xe[b0 * HD + lane * 4];
            float4 xb1 = *(const float4*)&g_Xe[b1 * HD + lane * 4];
            float4 xb2 = *(const float4*)&g_Xe[b2 * HD + lane * 4];
            float4 xb3 = *(const float4*)&g_Xe[b3 * HD + lane * 4];
            accA.x += (xa0.x + xa1.x) + (xa2.x + xa3.x);
            accA.y += (xa0.y + xa1.y) + (xa2.y + xa3.y);
            accA.z += (xa0.z + xa1.z) + (xa2.z + xa3.z);
            accA.w += (xa0.w + xa1.w) + (xa2.w + xa3.w);
            accB.x += (xb0.x + xb1.x) + (xb2.x + xb3.x);
            accB.y += (xb0.y + xb1.y) + (xb2.y + xb3.y);
            accB.z += (xb0.z + xb1.z) + (xb2.z + xb3.z);
            accB.w += (xb0.w + xb1.w) + (xb2.w + xb3.w);
            pA += 4; pB += 4;
        }
        // drains
        for (; pA + 4 <= eA; pA += 4) {
            int a0 = g_adj_v[pA], a1 = g_adj_v[pA + 1], a2 = g_adj_v[pA + 2], a3 = g_adj_v[pA + 3];
            float4 x0 = *(const float4*)&g_Xe[a0 * HD + lane * 4];
            float4 x1 = *(const float4*)&g_Xe[a1 * HD + lane * 4];
            float4 x2 = *(const float4*)&g_Xe[a2 * HD + lane * 4];
            float4 x3 = *(const float4*)&g_Xe[a3 * HD + lane * 4];
            accA.x += (x0.x + x1.x) + (x2.x + x3.x);
            accA.y += (x0.y + x1.y) + (x2.y + x3.y);
            accA.z += (x0.z + x1.z) + (x2.z + x3.z);
            accA.w += (x0.w + x1.w) + (x2.w + x3.w);
        }
        for (; pA < eA; pA++) {
            float4 x0 = *(const float4*)&g_Xe[g_adj_v[pA] * HD + lane * 4];
            accA.x += x0.x; accA.y += x0.y; accA.z += x0.z; accA.w += x0.w;
        }
        for (; pB + 4 <= eB; pB += 4) {
            int b0 = g_adj_v[pB], b1 = g_adj_v[pB + 1], b2 = g_adj_v[pB + 2], b3 = g_adj_v[pB + 3];
            float4 x0 = *(const float4*)&g_Xe[b0 * HD + lane * 4];
            float4 x1 = *(const float4*)&g_Xe[b1 * HD + lane * 4];
            float4 x2 = *(const float4*)&g_Xe[b2 * HD + lane * 4];
            float4 x3 = *(const float4*)&g_Xe[b3 * HD + lane * 4];
            accB.x += (x0.x + x1.x) + (x2.x + x3.x);
            accB.y += (x0.y + x1.y) + (x2.y + x3.y);
            accB.z += (x0.z + x1.z) + (x2.z + x3.z);
            accB.w += (x0.w + x1.w) + (x2.w + x3.w);
        }
        for (; pB < eB; pB++) {
            float4 x0 = *(const float4*)&g_Xe[g_adj_v[pB] * HD + lane * 4];
            accB.x += x0.x; accB.y += x0.y; accB.z += x0.z; accB.w += x0.w;
        }

        float ssA = accA.x * accA.x + accA.y * accA.y + accA.z * accA.z + accA.w * accA.w;
        float ssB = accB.x * accB.x + accB.y * accB.y + accB.z * accB.z + accB.w * accB.w;
        #pragma unroll
        for (int o = 16; o > 0; o >>= 1) {
            ssA += __shfl_xor_sync(0xffffffffu, ssA, o);
            ssB += __shfl_xor_sync(0xffffffffu, ssB, o);
        }
        float sA = (ssA > 0.f) ? (0.9f / sqrtf(ssA)) : 0.f;
        float sB = (ssB > 0.f) ? (0.9f / sqrtf(ssB)) : 0.f;
        float4 xoA = *(const float4*)&g_h0[vA * HD + lane * 4];
        float4 xoB = *(const float4*)&g_h0[vB * HD + lane * 4];
        float4 oA, oB;
        oA.x = accA.x * sA + 0.1f * xoA.x;
        oA.y = accA.y * sA + 0.1f * xoA.y;
        oA.z = accA.z * sA + 0.1f * xoA.z;
        oA.w = accA.w * sA + 0.1f * xoA.w;
        oB.x = accB.x * sB + 0.1f * xoB.x;
        oB.y = accB.y * sB + 0.1f * xoB.y;
        oB.z = accB.z * sB + 0.1f * xoB.z;
        oB.w = accB.w * sB + 0.1f * xoB.w;
        emit_row_frag(sAhi, sAlo, mA, lane, oA);
        emit_row_frag(sAhi, sAlo, mB, lane, oB);
    }
    __syncthreads();
    gemm_core_and_epilogue(dyn, nullptr, false, g_h, nullptr, m0, Mrows, tid);
}

// -------- output GEMM: [M,128] @ [128,40] + bias (f32x2 inner) ------------
__global__ __launch_bounds__(320) void gemm_out(
    const float* __restrict__ A, const float* __restrict__ W,
    const float* __restrict__ bias, float* __restrict__ C, int Mrows)
{
    __shared__ float xs[128][33];
    __shared__ float ws[128][40];
    int tid = threadIdx.x;
    int m0 = blockIdx.x * 128;

    for (int idx = tid; idx < 128 * 40; idx += 320)
        ws[idx / 40][idx % 40] = W[idx];

    int slot = tid / 5;
    int cg = tid % 5;
    int r0 = slot, r1 = slot + 64;

    u64 acc[2][4];
    #pragma unroll
    for (int r = 0; r < 2; r++)
        #pragma unroll
        for (int j = 0; j < 4; j++) acc[r][j] = 0ull;

    for (int kc = 0; kc < HD; kc += 32) {
        __syncthreads();
        for (int idx = tid; idx < 128 * 32; idx += 320) {
            int r = idx >> 5, k = idx & 31;
            int m = min(m0 + r, Mrows - 1);
            xs[r][k] = A[m * HD + kc + k];
        }
        __syncthreads();
        #pragma unroll
        for (int k = 0; k < 32; k++) {
            u64 aa0 = bcast2(xs[r0][k]);
            u64 aa1 = bcast2(xs[r1][k]);
            ulonglong2 wp0 = *(const ulonglong2*)&ws[kc + k][cg * 8];
            ulonglong2 wp1 = *(const ulonglong2*)&ws[kc + k][cg * 8 + 4];
            ffma2(acc[0][0], aa0, wp0.x, acc[0][0]);
            ffma2(acc[0][1], aa0, wp0.y, acc[0][1]);
            ffma2(acc[0][2], aa0, wp1.x, acc[0][2]);
            ffma2(acc[0][3], aa0, wp1.y, acc[0][3]);
            ffma2(acc[1][0], aa1, wp0.x, acc[1][0]);
            ffma2(acc[1][1], aa1, wp0.y, acc[1][1]);
            ffma2(acc[1][2], aa1, wp1.x, acc[1][2]);
            ffma2(acc[1][3], aa1, wp1.y, acc[1][3]);
        }
    }

    #pragma unroll
    for (int r = 0; r < 2; r++) {
        int m = m0 + (r ? r1 : r0);
        if (m < Mrows) {
            float v[8];
            #pragma unroll
            for (int j2 = 0; j2 < 4; j2++) {
                float2 f = unpack2(acc[r][j2]);
                v[j2 * 2 + 0] = f.x + bias[cg * 8 + j2 * 2 + 0];
                v[j2 * 2 + 1] = f.y + bias[cg * 8 + j2 * 2 + 1];
            }
            float4* dst = (float4*)&C[m * NCLS + cg * 8];
            dst[0] = *(float4*)&v[0];
            dst[1] = *(float4*)&v[4];
        }
    }
}

// ---------------------------------------------------------------------
extern "C" void kernel_launch(void* const* d_in, const int* in_sizes, int n_in,
                              void* d_out, int out_size) {
    const float* x    = (const float*)d_in[0];
    const float* W0   = (const float*)d_in[1];
    const float* b0   = (const float*)d_in[2];
    const float* Ws   = (const float*)d_in[3];
    const float* Wout = (const float*)d_in[4];
    const float* bout = (const float*)d_in[5];
    const int* vtx    = (const int*)d_in[6];
    const int* edg    = (const int*)d_in[7];
    float* out = (float*)d_out;

    float* h;
    cudaGetSymbolAddress((void**)&h, g_h);

    cudaFuncSetAttribute(gemm_mma0,
                         cudaFuncAttributeMaxDynamicSharedMemorySize, GB_SMEM);
    cudaFuncSetAttribute(gemm_fused,
                         cudaFuncAttributeMaxDynamicSharedMemorySize, GB_SMEM);

    const int gemmBlocks = (NV + 127) / 128;

    // CSR build
    k_zero_counts<<<(ME + NV + 255) / 256, 256>>>();
    k_count<<<(NNZE + 255) / 256, 256>>>(vtx, edg);
    k_scan<<<2, 1024>>>();
    k_fill<<<(NNZE + 255) / 256, 256>>>(vtx, edg);

    // weight prep: all 5 slots in one launch
    k_prep_frag<<<dim3((HD * HD + 255) / 256, 5), 256>>>(W0, Ws);

    // h = h0 = relu(x @ W0 + b0)
    gemm_mma0<<<gemmBlocks, 256, GB_SMEM>>>(x, b0, NV);

    for (int i = 0; i < DEPTH; i++) {
        k_edge_agg<<<(ME * 32 + 255) / 256, 256>>>();
        // h = relu( blend(norm(agg_v(Xe)), h0) @ W'[i] )  — agg fused in
        gemm_fused<<<gemmBlocks, 256, GB_SMEM>>>(i + 1, NV);
    }

    gemm_out<<<gemmBlocks, 320>>>(h, Wout, bout, out, NV);
}

// round 13
// speedup vs baseline: 1.2790x; 1.2790x over previous
#include <cuda_runtime.h>
#include <cuda_bf16.h>
#include <cstdint>
#include <math.h>

#define NV   100000
#define ME   50000
#define NNZE 800000
#define HD   128
#define NCLS 40
#define DEPTH 4

typedef unsigned long long u64;

// -------- scratch (no allocations allowed; __device__ globals) --------
__device__ float g_h [NV * HD];     // current features x
__device__ float g_h0[NV * HD];     // x0 (post first relu)
__device__ float g_Xe[ME * HD];     // edge features
// blended GEMM input, pre-split to bf16 hi/lo, row-major bf16x2 pairs
__device__ __align__(16) uint32_t g_Xhi[NV * 64];
__device__ __align__(16) uint32_t g_Xlo[NV * 64];
// weights pre-split to bf16 hi/lo in MMA fragment layout. slot0=W0, 1..4=folded
__device__ __align__(16) __nv_bfloat16 g_Bhi[5 * HD * HD];
__device__ __align__(16) __nv_bfloat16 g_Blo[5 * HD * HD];
__device__ int g_cnt_e[ME], g_cnt_v[NV];
__device__ int g_off_e[ME + 1], g_off_v[NV + 1];
__device__ int g_cur_e[ME], g_cur_v[NV];
__device__ int g_adj_e[NNZE];   // vertex ids grouped by edge
__device__ int g_adj_v[NNZE];   // edge ids grouped by vertex

// -------- f32x2 helpers (used by gemm_out) -----------------------------
__device__ __forceinline__ void ffma2(u64& d, u64 a, u64 b, u64 c) {
    asm("fma.rn.f32x2 %0, %1, %2, %3;" : "=l"(d) : "l"(a), "l"(b), "l"(c));
}
__device__ __forceinline__ u64 bcast2(float a) {
    u64 r;
    asm("mov.b64 %0, {%1, %1};" : "=l"(r) : "f"(a));
    return r;
}
__device__ __forceinline__ float2 unpack2(u64 u) {
    float2 f;
    asm("mov.b64 {%0, %1}, %2;" : "=f"(f.x), "=f"(f.y) : "l"(u));
    return f;
}

// -------- bf16 split helpers -------------------------------------------
__device__ __forceinline__ void bsplit(float a, __nv_bfloat16& hi, __nv_bfloat16& lo) {
    hi = __float2bfloat16_rn(a);
    lo = __float2bfloat16_rn(a - __bfloat162float(hi));
}
__device__ __forceinline__ uint32_t packbf(__nv_bfloat16 a, __nv_bfloat16 b) {
    __nv_bfloat162 p;
    p.x = a; p.y = b;
    return *(uint32_t*)&p;
}

// mma.sync m16n8k16 bf16 -> f32 accum (baseline PTX, no arch suffix)
__device__ __forceinline__ void mma16816(float* d, const uint4& a, const uint2& b) {
    asm volatile(
        "mma.sync.aligned.m16n8k16.row.col.f32.bf16.bf16.f32 "
        "{%0,%1,%2,%3}, {%4,%5,%6,%7}, {%8,%9}, {%0,%1,%2,%3};"
        : "+f"(d[0]), "+f"(d[1]), "+f"(d[2]), "+f"(d[3])
        : "r"(a.x), "r"(a.y), "r"(a.z), "r"(a.w), "r"(b.x), "r"(b.y));
}

// ---------------------------------------------------------------------
__global__ void k_zero_counts() {
    int i = blockIdx.x * blockDim.x + threadIdx.x;
    if (i < ME) g_cnt_e[i] = 0;
    if (i < NV) g_cnt_v[i] = 0;
}

__global__ void k_count(const int* __restrict__ vtx, const int* __restrict__ edg) {
    int i = blockIdx.x * blockDim.x + threadIdx.x;
    if (i >= NNZE) return;
    atomicAdd(&g_cnt_e[edg[i]], 1);
    atomicAdd(&g_cnt_v[vtx[i]], 1);
}

__global__ void k_scan() {
    const int which = blockIdx.x;
    const int len = which ? NV : ME;
    const int* cnt = which ? g_cnt_v : g_cnt_e;
    int* off = which ? g_off_v : g_off_e;
    int* cur = which ? g_cur_v : g_cur_e;

    __shared__ int sm[1024];
    int t = threadIdx.x;
    int chunk = (len + 1023) >> 10;
    int lo = t * chunk;
    int hi = min(lo + chunk, len);

    int s = 0;
    for (int i = lo; i < hi; i++) s += cnt[i];
    sm[t] = s;
    __syncthreads();
    for (int o = 1; o < 1024; o <<= 1) {
        int add = (t >= o) ? sm[t - o] : 0;
        __syncthreads();
        sm[t] += add;
        __syncthreads();
    }
    int excl = sm[t] - s;
    int run = excl;
    for (int i = lo; i < hi; i++) {
        off[i] = run;
        cur[i] = run;
        run += cnt[i];
    }
    if (t == 1023) off[len] = run;
}

__global__ void k_fill(const int* __restrict__ vtx, const int* __restrict__ edg) {
    int i = blockIdx.x * blockDim.x + threadIdx.x;
    if (i >= NNZE) return;
    int e = edg[i], v = vtx[i];
    int pe = atomicAdd(&g_cur_e[e], 1);
    g_adj_e[pe] = v;
    int pv = atomicAdd(&g_cur_v[v], 1);
    g_adj_v[pv] = e;
}

// -------- weight prep (all 5 slots in one launch, grid.y = slot) --------
__global__ void k_prep_frag(const float* __restrict__ W0, const float* __restrict__ Ws) {
    int slot = blockIdx.y;
    int idx = blockIdx.x * blockDim.x + threadIdx.x;
    if (idx >= HD * HD) return;
    const float* W = (slot == 0) ? W0 : Ws + (slot - 1) * HD * HD;
    int k = idx >> 7, n = idx & 127;
    float w = W[idx];
    if (slot > 0) {
        float beta = logf(0.5f / (float)slot + 1.0f);
        w = beta * w;
        if (k == n) w += (1.0f - beta);
    }
    __nv_bfloat16 hi, lo;
    bsplit(w, hi, lo);
    int kt = k >> 4, kc = k & 15;
    int nt = n >> 3, nc = n & 7;
    int lane = nc * 4 + ((kc & 7) >> 1);
    int elem = ((kt * 16 + nt) * 32 + lane) * 4 + ((kc >> 3) << 1) + (kc & 1);
    g_Bhi[slot * HD * HD + elem] = hi;
    g_Blo[slot * HD * HD + elem] = lo;
}

// -------- edge aggregation: warp per edge, gather-only, MLP-8 -----------
__global__ __launch_bounds__(256) void k_edge_agg() {
    int e = (blockIdx.x * blockDim.x + threadIdx.x) >> 5;
    if (e >= ME) return;
    int lane = threadIdx.x & 31;
    int beg = g_off_e[e], end = g_off_e[e + 1];
    float4 acc = make_float4(0.f, 0.f, 0.f, 0.f);
    int p = beg;
    for (; p + 8 <= end; p += 8) {
        int v0 = g_adj_e[p],     v1 = g_adj_e[p + 1];
        int v2 = g_adj_e[p + 2], v3 = g_adj_e[p + 3];
        int v4 = g_adj_e[p + 4], v5 = g_adj_e[p + 5];
        int v6 = g_adj_e[p + 6], v7 = g_adj_e[p + 7];
        float4 a = *(const float4*)&g_h[v0 * HD + lane * 4];
        float4 b = *(const float4*)&g_h[v1 * HD + lane * 4];
        float4 c = *(const float4*)&g_h[v2 * HD + lane * 4];
        float4 d = *(const float4*)&g_h[v3 * HD + lane * 4];
        float4 ee = *(const float4*)&g_h[v4 * HD + lane * 4];
        float4 f = *(const float4*)&g_h[v5 * HD + lane * 4];
        float4 g = *(const float4*)&g_h[v6 * HD + lane * 4];
        float4 hh = *(const float4*)&g_h[v7 * HD + lane * 4];
        acc.x += (a.x + b.x) + (c.x + d.x) + (ee.x + f.x) + (g.x + hh.x);
        acc.y += (a.y + b.y) + (c.y + d.y) + (ee.y + f.y) + (g.y + hh.y);
        acc.z += (a.z + b.z) + (c.z + d.z) + (ee.z + f.z) + (g.z + hh.z);
        acc.w += (a.w + b.w) + (c.w + d.w) + (ee.w + f.w) + (g.w + hh.w);
    }
    for (; p + 4 <= end; p += 4) {
        int v0 = g_adj_e[p], v1 = g_adj_e[p + 1], v2 = g_adj_e[p + 2], v3 = g_adj_e[p + 3];
        float4 a = *(const float4*)&g_h[v0 * HD + lane * 4];
        float4 b = *(const float4*)&g_h[v1 * HD + lane * 4];
        float4 c = *(const float4*)&g_h[v2 * HD + lane * 4];
        float4 d = *(const float4*)&g_h[v3 * HD + lane * 4];
        acc.x += (a.x + b.x) + (c.x + d.x);
        acc.y += (a.y + b.y) + (c.y + d.y);
        acc.z += (a.z + b.z) + (c.z + d.z);
        acc.w += (a.w + b.w) + (c.w + d.w);
    }
    for (; p < end; p++) {
        int v = g_adj_e[p];
        float4 a = *(const float4*)&g_h[v * HD + lane * 4];
        acc.x += a.x; acc.y += a.y; acc.z += a.z; acc.w += a.w;
    }
    float inv = 1.0f / (float)max(end - beg, 1);
    acc.x *= inv; acc.y *= inv; acc.z *= inv; acc.w *= inv;
    *(float4*)&g_Xe[e * HD + lane * 4] = acc;
}

// vertex agg + L2-normalize + alpha blend + bf16 hi/lo split.
// Writes row-major bf16x2 pair arrays (coalesced uint2 stores); the split
// ALU hides under gather latency (kernel is issue-bound <5%).
__global__ __launch_bounds__(256) void k_vert_agg() {
    int v = (blockIdx.x * blockDim.x + threadIdx.x) >> 5;
    if (v >= NV) return;
    int lane = threadIdx.x & 31;
    int beg = g_off_v[v], end = g_off_v[v + 1];
    float4 acc = make_float4(0.f, 0.f, 0.f, 0.f);
    int p = beg;
    for (; p + 8 <= end; p += 8) {
        int e0 = g_adj_v[p],     e1 = g_adj_v[p + 1];
        int e2 = g_adj_v[p + 2], e3 = g_adj_v[p + 3];
        int e4 = g_adj_v[p + 4], e5 = g_adj_v[p + 5];
        int e6 = g_adj_v[p + 6], e7 = g_adj_v[p + 7];
        float4 a = *(const float4*)&g_Xe[e0 * HD + lane * 4];
        float4 b = *(const float4*)&g_Xe[e1 * HD + lane * 4];
        float4 c = *(const float4*)&g_Xe[e2 * HD + lane * 4];
        float4 d = *(const float4*)&g_Xe[e3 * HD + lane * 4];
        float4 ee = *(const float4*)&g_Xe[e4 * HD + lane * 4];
        float4 f = *(const float4*)&g_Xe[e5 * HD + lane * 4];
        float4 g = *(const float4*)&g_Xe[e6 * HD + lane * 4];
        float4 hh = *(const float4*)&g_Xe[e7 * HD + lane * 4];
        acc.x += (a.x + b.x) + (c.x + d.x) + (ee.x + f.x) + (g.x + hh.x);
        acc.y += (a.y + b.y) + (c.y + d.y) + (ee.y + f.y) + (g.y + hh.y);
        acc.z += (a.z + b.z) + (c.z + d.z) + (ee.z + f.z) + (g.z + hh.z);
        acc.w += (a.w + b.w) + (c.w + d.w) + (ee.w + f.w) + (g.w + hh.w);
    }
    for (; p + 4 <= end; p += 4) {
        int e0 = g_adj_v[p], e1 = g_adj_v[p + 1], e2 = g_adj_v[p + 2], e3 = g_adj_v[p + 3];
        float4 a = *(const float4*)&g_Xe[e0 * HD + lane * 4];
        float4 b = *(const float4*)&g_Xe[e1 * HD + lane * 4];
        float4 c = *(const float4*)&g_Xe[e2 * HD + lane * 4];
        float4 d = *(const float4*)&g_Xe[e3 * HD + lane * 4];
        acc.x += (a.x + b.x) + (c.x + d.x);
        acc.y += (a.y + b.y) + (c.y + d.y);
        acc.z += (a.z + b.z) + (c.z + d.z);
        acc.w += (a.w + b.w) + (c.w + d.w);
    }
    for (; p < end; p++) {
        int e = g_adj_v[p];
        float4 a = *(const float4*)&g_Xe[e * HD + lane * 4];
        acc.x += a.x; acc.y += a.y; acc.z += a.z; acc.w += a.w;
    }
    float ss = acc.x * acc.x + acc.y * acc.y + acc.z * acc.z + acc.w * acc.w;
    #pragma unroll
    for (int o = 16; o > 0; o >>= 1) ss += __shfl_xor_sync(0xffffffffu, ss, o);
    float s9 = (ss > 0.f) ? (0.9f / sqrtf(ss)) : 0.f;
    float4 x0 = *(const float4*)&g_h0[v * HD + lane * 4];
    float4 o;
    o.x = acc.x * s9 + 0.1f * x0.x;
    o.y = acc.y * s9 + 0.1f * x0.y;
    o.z = acc.z * s9 + 0.1f * x0.z;
    o.w = acc.w * s9 + 0.1f * x0.w;
    // split to bf16 hi/lo pairs; lane owns k = lane*4..+3 -> pairs 2*lane, 2*lane+1
    __nv_bfloat16 h0b, l0b, h1b, l1b, h2b, l2b, h3b, l3b;
    bsplit(o.x, h0b, l0b);
    bsplit(o.y, h1b, l1b);
    bsplit(o.z, h2b, l2b);
    bsplit(o.w, h3b, l3b);
    uint2 uhi, ulo;
    uhi.x = packbf(h0b, h1b); uhi.y = packbf(h2b, h3b);
    ulo.x = packbf(l0b, l1b); ulo.y = packbf(l2b, l3b);
    ((uint2*)g_Xhi)[v * 32 + lane] = uhi;
    ((uint2*)g_Xlo)[v * 32 + lane] = ulo;
}

// ---- MMA GEMM shared pieces --------------------------------------------
#define GB_SMEM (4 * 8192 * 4)

__device__ __forceinline__ void gemm_core_and_epilogue(
    uint32_t* dyn, const float* bias, bool hasBias,
    float* C, float* C2, int m0, int Mrows, int tid)
{
    uint32_t* sAhi = dyn;
    uint32_t* sAlo = dyn + 8192;
    uint32_t* sBhi = dyn + 16384;
    uint32_t* sBlo = dyn + 24576;

    int wid = tid >> 5;
    int lane = tid & 31;
    int mwarp = wid & 3;
    int nwarp = wid >> 2;
    int mt0 = mwarp * 2;
    int nt0 = nwarp * 8;

    float acc[2][8][4];
    #pragma unroll
    for (int i = 0; i < 2; i++)
        #pragma unroll
        for (int j = 0; j < 8; j++)
            #pragma unroll
            for (int q = 0; q < 4; q++) acc[i][j][q] = 0.f;

    #pragma unroll 1
    for (int seg = 0; seg < 3; seg++) {
        const uint4* aBuf = (const uint4*)(seg == 1 ? sAlo : sAhi);
        const uint2* bBuf = (const uint2*)(seg == 2 ? sBlo : sBhi);
        #pragma unroll 1
        for (int kt = 0; kt < 8; kt++) {
            uint4 afr[2];
            afr[0] = aBuf[(kt * 8 + mt0) * 32 + lane];
            afr[1] = aBuf[(kt * 8 + mt0 + 1) * 32 + lane];
            uint2 bfr[8];
            #pragma unroll
            for (int j = 0; j < 8; j++)
                bfr[j] = bBuf[(kt * 16 + nt0 + j) * 32 + lane];
            #pragma unroll
            for (int i = 0; i < 2; i++)
                #pragma unroll
                for (int j = 0; j < 8; j++)
                    mma16816(acc[i][j], afr[i], bfr[j]);
        }
    }

    int rbase = m0 + mwarp * 32 + (lane >> 2);
    int cbase = nwarp * 64 + (lane & 3) * 2;
    #pragma unroll
    for (int i = 0; i < 2; i++) {
        #pragma unroll
        for (int j = 0; j < 8; j++) {
            int col = cbase + j * 8;
            float bx = hasBias ? bias[col] : 0.f;
            float by = hasBias ? bias[col + 1] : 0.f;
            int r0 = rbase + i * 16;
            if (r0 < Mrows) {
                float2 v;
                v.x = fmaxf(acc[i][j][0] + bx, 0.f);
                v.y = fmaxf(acc[i][j][1] + by, 0.f);
                *(float2*)&C[r0 * HD + col] = v;
                if (C2) *(float2*)&C2[r0 * HD + col] = v;
            }
            int r1 = rbase + i * 16 + 8;
            if (r1 < Mrows) {
                float2 v;
                v.x = fmaxf(acc[i][j][2] + bx, 0.f);
                v.y = fmaxf(acc[i][j][3] + by, 0.f);
                *(float2*)&C[r1 * HD + col] = v;
                if (C2) *(float2*)&C2[r1 * HD + col] = v;
            }
        }
    }
}

__device__ __forceinline__ void stage_B(uint32_t* dyn, int slot, int tid) {
    const uint4* srcH = (const uint4*)(g_Bhi + slot * HD * HD);
    const uint4* srcL = (const uint4*)(g_Blo + slot * HD * HD);
    uint4* dstH = (uint4*)(dyn + 16384);
    uint4* dstL = (uint4*)(dyn + 24576);
    #pragma unroll
    for (int it = 0; it < 8; it++) {
        dstH[tid + it * 256] = srcH[tid + it * 256];
        dstL[tid + it * 256] = srcL[tid + it * 256];
    }
}

// ---- layer-0 GEMM: h = h0 = relu(x @ W0 + b0), A from fp32 gmem --------
__global__ __launch_bounds__(256, 1) void gemm_mma0(
    const float* __restrict__ A, const float* __restrict__ bias, int Mrows)
{
    extern __shared__ uint32_t dyn[];
    int tid = threadIdx.x;
    int m0 = blockIdx.x * 128;

    stage_B(dyn, 0, tid);
    {
        uint32_t* sAhi = dyn;
        uint32_t* sAlo = dyn + 8192;
        #pragma unroll
        for (int it = 0; it < 32; it++) {
            int idx2 = tid + it * 256;
            int m = idx2 >> 6;
            int k = (idx2 & 63) * 2;
            int gm = min(m0 + m, Mrows - 1);
            float2 a = *(const float2*)&A[gm * HD + k];
            __nv_bfloat16 h0b, l0b, h1b, l1b;
            bsplit(a.x, h0b, l0b);
            bsplit(a.y, h1b, l1b);
            int kt = k >> 4, kc = k & 15;
            int mt = m >> 4, r = m & 15;
            int lane = (r & 7) * 4 + ((kc & 7) >> 1);
            int reg = (r >> 3) + ((kc >> 3) << 1);
            int w32 = (((kt * 8 + mt) * 32 + lane) << 2) + reg;
            sAhi[w32] = packbf(h0b, h1b);
            sAlo[w32] = packbf(l0b, l1b);
        }
    }
    __syncthreads();
    gemm_core_and_epilogue(dyn, bias, true, g_h, g_h0, m0, Mrows, tid);
}

// ---- layer GEMM: h = relu(Xi @ W'), A pre-split by k_vert_agg ----------
// A-staging is a pure permutation copy: row-major bf16x2 pair words are
// bit-identical to frag u32 elements; only the address changes.
// Row = 64 pairs = 16 uint4s; uint4 q covers k = 8q..8q+7.
__global__ __launch_bounds__(256, 1) void gemm_layer(int slot, int Mrows)
{
    extern __shared__ uint32_t dyn[];
    int tid = threadIdx.x;
    int m0 = blockIdx.x * 128;

    stage_B(dyn, slot, tid);
    {
        uint32_t* sAhi = dyn;
        uint32_t* sAlo = dyn + 8192;
        #pragma unroll
        for (int it = 0; it < 8; it++) {
            int idx = tid + it * 256;         // uint4 index (2048 total)
            int m = idx >> 4;                 // row 0..127
            int q = idx & 15;                 // uint4 within row (16 per row)
            int v = min(m0 + m, Mrows - 1);
            uint4 hi4 = ((const uint4*)(g_Xhi + v * 64))[q];
            uint4 lo4 = ((const uint4*)(g_Xlo + v * 64))[q];
            int mt = m >> 4, r = m & 15;
            int kt = q >> 1;                  // k-tile 0..7
            int reg = (r >> 3) + ((q & 1) << 1);
            int base = ((kt * 8 + mt) * 32 + (r & 7) * 4) << 2;
            sAhi[base + reg]      = hi4.x;
            sAhi[base + 4 + reg]  = hi4.y;
            sAhi[base + 8 + reg]  = hi4.z;
            sAhi[base + 12 + reg] = hi4.w;
            sAlo[base + reg]      = lo4.x;
            sAlo[base + 4 + reg]  = lo4.y;
            sAlo[base + 8 + reg]  = lo4.z;
            sAlo[base + 12 + reg] = lo4.w;
        }
    }
    __syncthreads();
    gemm_core_and_epilogue(dyn, nullptr, false, g_h, nullptr, m0, Mrows, tid);
}

// -------- output GEMM: [M,128] @ [128,40] + bias (f32x2 inner) ------------
__global__ __launch_bounds__(320) void gemm_out(
    const float* __restrict__ A, const float* __restrict__ W,
    const float* __restrict__ bias, float* __restrict__ C, int Mrows)
{
    __shared__ float xs[128][33];
    __shared__ float ws[128][40];
    int tid = threadIdx.x;
    int m0 = blockIdx.x * 128;

    for (int idx = tid; idx < 128 * 40; idx += 320)
        ws[idx / 40][idx % 40] = W[idx];

    int slot = tid / 5;
    int cg = tid % 5;
    int r0 = slot, r1 = slot + 64;

    u64 acc[2][4];
    #pragma unroll
    for (int r = 0; r < 2; r++)
        #pragma unroll
        for (int j = 0; j < 4; j++) acc[r][j] = 0ull;

    for (int kc = 0; kc < HD; kc += 32) {
        __syncthreads();
        for (int idx = tid; idx < 128 * 32; idx += 320) {
            int r = idx >> 5, k = idx & 31;
            int m = min(m0 + r, Mrows - 1);
            xs[r][k] = A[m * HD + kc + k];
        }
        __syncthreads();
        #pragma unroll
        for (int k = 0; k < 32; k++) {
            u64 aa0 = bcast2(xs[r0][k]);
            u64 aa1 = bcast2(xs[r1][k]);
            ulonglong2 wp0 = *(const ulonglong2*)&ws[kc + k][cg * 8];
            ulonglong2 wp1 = *(const ulonglong2*)&ws[kc + k][cg * 8 + 4];
            ffma2(acc[0][0], aa0, wp0.x, acc[0][0]);
            ffma2(acc[0][1], aa0, wp0.y, acc[0][1]);
            ffma2(acc[0][2], aa0, wp1.x, acc[0][2]);
            ffma2(acc[0][3], aa0, wp1.y, acc[0][3]);
            ffma2(acc[1][0], aa1, wp0.x, acc[1][0]);
            ffma2(acc[1][1], aa1, wp0.y, acc[1][1]);
            ffma2(acc[1][2], aa1, wp1.x, acc[1][2]);
            ffma2(acc[1][3], aa1, wp1.y, acc[1][3]);
        }
    }

    #pragma unroll
    for (int r = 0; r < 2; r++) {
        int m = m0 + (r ? r1 : r0);
        if (m < Mrows) {
            float v[8];
            #pragma unroll
            for (int j2 = 0; j2 < 4; j2++) {
                float2 f = unpack2(acc[r][j2]);
                v[j2 * 2 + 0] = f.x + bias[cg * 8 + j2 * 2 + 0];
                v[j2 * 2 + 1] = f.y + bias[cg * 8 + j2 * 2 + 1];
            }
            float4* dst = (float4*)&C[m * NCLS + cg * 8];
            dst[0] = *(float4*)&v[0];
            dst[1] = *(float4*)&v[4];
        }
    }
}

// ---------------------------------------------------------------------
extern "C" void kernel_launch(void* const* d_in, const int* in_sizes, int n_in,
                              void* d_out, int out_size) {
    const float* x    = (const float*)d_in[0];
    const float* W0   = (const float*)d_in[1];
    const float* b0   = (const float*)d_in[2];
    const float* Ws   = (const float*)d_in[3];
    const float* Wout = (const float*)d_in[4];
    const float* bout = (const float*)d_in[5];
    const int* vtx    = (const int*)d_in[6];
    const int* edg    = (const int*)d_in[7];
    float* out = (float*)d_out;

    float* h;
    cudaGetSymbolAddress((void**)&h, g_h);

    cudaFuncSetAttribute(gemm_mma0,
                         cudaFuncAttributeMaxDynamicSharedMemorySize, GB_SMEM);
    cudaFuncSetAttribute(gemm_layer,
                         cudaFuncAttributeMaxDynamicSharedMemorySize, GB_SMEM);

    const int gemmBlocks = (NV + 127) / 128;

    // CSR build
    k_zero_counts<<<(ME + NV + 255) / 256, 256>>>();
    k_count<<<(NNZE + 255) / 256, 256>>>(vtx, edg);
    k_scan<<<2, 1024>>>();
    k_fill<<<(NNZE + 255) / 256, 256>>>(vtx, edg);

    // weight prep: all 5 slots in one launch
    k_prep_frag<<<dim3((HD * HD + 255) / 256, 5), 256>>>(W0, Ws);

    // h = h0 = relu(x @ W0 + b0)
    gemm_mma0<<<gemmBlocks, 256, GB_SMEM>>>(x, b0, NV);

    for (int i = 0; i < DEPTH; i++) {
        k_edge_agg<<<(ME * 32 + 255) / 256, 256>>>();
        k_vert_agg<<<(NV * 32 + 255) / 256, 256>>>();
        // h = relu(Xi @ ((1-b)I + b*Ws[i]))
        gemm_layer<<<gemmBlocks, 256, GB_SMEM>>>(i + 1, NV);
    }

    gemm_out<<<gemmBlocks, 320>>>(h, Wout, bout, out, NV);
}

// round 14
// speedup vs baseline: 1.2813x; 1.0019x over previous
#include <cuda_runtime.h>
#include <cuda_bf16.h>
#include <cstdint>
#include <math.h>

#define NV   100000
#define ME   50000
#define NNZE 800000
#define HD   128
#define NCLS 40
#define DEPTH 4

typedef unsigned long long u64;

// -------- scratch (no allocations allowed; __device__ globals) --------
__device__ float g_h [NV * HD];     // current features x
__device__ float g_h0[NV * HD];     // x0 (post first relu)
__device__ float g_Xe[ME * HD];     // edge features
// blended GEMM input, pre-split to bf16 hi/lo, row-major bf16x2 pairs
__device__ __align__(16) uint32_t g_Xhi[NV * 64];
__device__ __align__(16) uint32_t g_Xlo[NV * 64];
// weights pre-split to bf16 hi/lo in MMA fragment layout. slot0=W0, 1..4=folded
__device__ __align__(16) __nv_bfloat16 g_Bhi[5 * HD * HD];
__device__ __align__(16) __nv_bfloat16 g_Blo[5 * HD * HD];
__device__ int g_cnt_e[ME], g_cnt_v[NV];
__device__ int g_off_e[ME + 1], g_off_v[NV + 1];
__device__ int g_cur_e[ME], g_cur_v[NV];
__device__ int g_adj_e[NNZE];   // vertex ids grouped by edge
__device__ int g_adj_v[NNZE];   // edge ids grouped by vertex

// -------- f32x2 helpers (used by gemm_out) -----------------------------
__device__ __forceinline__ void ffma2(u64& d, u64 a, u64 b, u64 c) {
    asm("fma.rn.f32x2 %0, %1, %2, %3;" : "=l"(d) : "l"(a), "l"(b), "l"(c));
}
__device__ __forceinline__ u64 bcast2(float a) {
    u64 r;
    asm("mov.b64 %0, {%1, %1};" : "=l"(r) : "f"(a));
    return r;
}
__device__ __forceinline__ float2 unpack2(u64 u) {
    float2 f;
    asm("mov.b64 {%0, %1}, %2;" : "=f"(f.x), "=f"(f.y) : "l"(u));
    return f;
}

// -------- bf16 split helpers -------------------------------------------
__device__ __forceinline__ void bsplit(float a, __nv_bfloat16& hi, __nv_bfloat16& lo) {
    hi = __float2bfloat16_rn(a);
    lo = __float2bfloat16_rn(a - __bfloat162float(hi));
}
__device__ __forceinline__ uint32_t packbf(__nv_bfloat16 a, __nv_bfloat16 b) {
    __nv_bfloat162 p;
    p.x = a; p.y = b;
    return *(uint32_t*)&p;
}

// mma.sync m16n8k16 bf16 -> f32 accum (baseline PTX, no arch suffix)
__device__ __forceinline__ void mma16816(float* d, const uint4& a, const uint2& b) {
    asm volatile(
        "mma.sync.aligned.m16n8k16.row.col.f32.bf16.bf16.f32 "
        "{%0,%1,%2,%3}, {%4,%5,%6,%7}, {%8,%9}, {%0,%1,%2,%3};"
        : "+f"(d[0]), "+f"(d[1]), "+f"(d[2]), "+f"(d[3])
        : "r"(a.x), "r"(a.y), "r"(a.z), "r"(a.w), "r"(b.x), "r"(b.y));
}

// ---------------------------------------------------------------------
__global__ void k_zero_counts() {
    int i = blockIdx.x * blockDim.x + threadIdx.x;
    if (i < ME) g_cnt_e[i] = 0;
    if (i < NV) g_cnt_v[i] = 0;
}

__global__ void k_count(const int* __restrict__ vtx, const int* __restrict__ edg) {
    int i = blockIdx.x * blockDim.x + threadIdx.x;
    if (i >= NNZE) return;
    atomicAdd(&g_cnt_e[edg[i]], 1);
    atomicAdd(&g_cnt_v[vtx[i]], 1);
}

__global__ void k_scan() {
    const int which = blockIdx.x;
    const int len = which ? NV : ME;
    const int* cnt = which ? g_cnt_v : g_cnt_e;
    int* off = which ? g_off_v : g_off_e;
    int* cur = which ? g_cur_v : g_cur_e;

    __shared__ int sm[1024];
    int t = threadIdx.x;
    int chunk = (len + 1023) >> 10;
    int lo = t * chunk;
    int hi = min(lo + chunk, len);

    int s = 0;
    for (int i = lo; i < hi; i++) s += cnt[i];
    sm[t] = s;
    __syncthreads();
    for (int o = 1; o < 1024; o <<= 1) {
        int add = (t >= o) ? sm[t - o] : 0;
        __syncthreads();
        sm[t] += add;
        __syncthreads();
    }
    int excl = sm[t] - s;
    int run = excl;
    for (int i = lo; i < hi; i++) {
        off[i] = run;
        cur[i] = run;
        run += cnt[i];
    }
    if (t == 1023) off[len] = run;
}

__global__ void k_fill(const int* __restrict__ vtx, const int* __restrict__ edg) {
    int i = blockIdx.x * blockDim.x + threadIdx.x;
    if (i >= NNZE) return;
    int e = edg[i], v = vtx[i];
    int pe = atomicAdd(&g_cur_e[e], 1);
    g_adj_e[pe] = v;
    int pv = atomicAdd(&g_cur_v[v], 1);
    g_adj_v[pv] = e;
}

// -------- weight prep (all 5 slots in one launch, grid.y = slot) --------
__global__ void k_prep_frag(const float* __restrict__ W0, const float* __restrict__ Ws) {
    int slot = blockIdx.y;
    int idx = blockIdx.x * blockDim.x + threadIdx.x;
    if (idx >= HD * HD) return;
    const float* W = (slot == 0) ? W0 : Ws + (slot - 1) * HD * HD;
    int k = idx >> 7, n = idx & 127;
    float w = W[idx];
    if (slot > 0) {
        float beta = logf(0.5f / (float)slot + 1.0f);
        w = beta * w;
        if (k == n) w += (1.0f - beta);
    }
    __nv_bfloat16 hi, lo;
    bsplit(w, hi, lo);
    int kt = k >> 4, kc = k & 15;
    int nt = n >> 3, nc = n & 7;
    int lane = nc * 4 + ((kc & 7) >> 1);
    int elem = ((kt * 16 + nt) * 32 + lane) * 4 + ((kc >> 3) << 1) + (kc & 1);
    g_Bhi[slot * HD * HD + elem] = hi;
    g_Blo[slot * HD * HD + elem] = lo;
}

// -------- edge aggregation: warp per edge, gather-only, MLP-8 -----------
__global__ __launch_bounds__(256) void k_edge_agg() {
    int e = (blockIdx.x * blockDim.x + threadIdx.x) >> 5;
    if (e >= ME) return;
    int lane = threadIdx.x & 31;
    int beg = g_off_e[e], end = g_off_e[e + 1];
    float4 acc = make_float4(0.f, 0.f, 0.f, 0.f);
    int p = beg;
    for (; p + 8 <= end; p += 8) {
        int v0 = g_adj_e[p],     v1 = g_adj_e[p + 1];
        int v2 = g_adj_e[p + 2], v3 = g_adj_e[p + 3];
        int v4 = g_adj_e[p + 4], v5 = g_adj_e[p + 5];
        int v6 = g_adj_e[p + 6], v7 = g_adj_e[p + 7];
        float4 a = *(const float4*)&g_h[v0 * HD + lane * 4];
        float4 b = *(const float4*)&g_h[v1 * HD + lane * 4];
        float4 c = *(const float4*)&g_h[v2 * HD + lane * 4];
        float4 d = *(const float4*)&g_h[v3 * HD + lane * 4];
        float4 ee = *(const float4*)&g_h[v4 * HD + lane * 4];
        float4 f = *(const float4*)&g_h[v5 * HD + lane * 4];
        float4 g = *(const float4*)&g_h[v6 * HD + lane * 4];
        float4 hh = *(const float4*)&g_h[v7 * HD + lane * 4];
        acc.x += (a.x + b.x) + (c.x + d.x) + (ee.x + f.x) + (g.x + hh.x);
        acc.y += (a.y + b.y) + (c.y + d.y) + (ee.y + f.y) + (g.y + hh.y);
        acc.z += (a.z + b.z) + (c.z + d.z) + (ee.z + f.z) + (g.z + hh.z);
        acc.w += (a.w + b.w) + (c.w + d.w) + (ee.w + f.w) + (g.w + hh.w);
    }
    for (; p + 4 <= end; p += 4) {
        int v0 = g_adj_e[p], v1 = g_adj_e[p + 1], v2 = g_adj_e[p + 2], v3 = g_adj_e[p + 3];
        float4 a = *(const float4*)&g_h[v0 * HD + lane * 4];
        float4 b = *(const float4*)&g_h[v1 * HD + lane * 4];
        float4 c = *(const float4*)&g_h[v2 * HD + lane * 4];
        float4 d = *(const float4*)&g_h[v3 * HD + lane * 4];
        acc.x += (a.x + b.x) + (c.x + d.x);
        acc.y += (a.y + b.y) + (c.y + d.y);
        acc.z += (a.z + b.z) + (c.z + d.z);
        acc.w += (a.w + b.w) + (c.w + d.w);
    }
    for (; p < end; p++) {
        int v = g_adj_e[p];
        float4 a = *(const float4*)&g_h[v * HD + lane * 4];
        acc.x += a.x; acc.y += a.y; acc.z += a.z; acc.w += a.w;
    }
    float inv = 1.0f / (float)max(end - beg, 1);
    acc.x *= inv; acc.y *= inv; acc.z *= inv; acc.w *= inv;
    *(float4*)&g_Xe[e * HD + lane * 4] = acc;
}

// vertex agg + L2-normalize + alpha blend + bf16 hi/lo split.
// Writes row-major bf16x2 pair arrays (coalesced uint2 stores); the split
// ALU hides under gather latency (kernel is issue-bound <5%).
__global__ __launch_bounds__(256) void k_vert_agg() {
    int v = (blockIdx.x * blockDim.x + threadIdx.x) >> 5;
    if (v >= NV) return;
    int lane = threadIdx.x & 31;
    int beg = g_off_v[v], end = g_off_v[v + 1];
    float4 acc = make_float4(0.f, 0.f, 0.f, 0.f);
    int p = beg;
    for (; p + 8 <= end; p += 8) {
        int e0 = g_adj_v[p],     e1 = g_adj_v[p + 1];
        int e2 = g_adj_v[p + 2], e3 = g_adj_v[p + 3];
        int e4 = g_adj_v[p + 4], e5 = g_adj_v[p + 5];
        int e6 = g_adj_v[p + 6], e7 = g_adj_v[p + 7];
        float4 a = *(const float4*)&g_Xe[e0 * HD + lane * 4];
        float4 b = *(const float4*)&g_Xe[e1 * HD + lane * 4];
        float4 c = *(const float4*)&g_Xe[e2 * HD + lane * 4];
        float4 d = *(const float4*)&g_Xe[e3 * HD + lane * 4];
        float4 ee = *(const float4*)&g_Xe[e4 * HD + lane * 4];
        float4 f = *(const float4*)&g_Xe[e5 * HD + lane * 4];
        float4 g = *(const float4*)&g_Xe[e6 * HD + lane * 4];
        float4 hh = *(const float4*)&g_Xe[e7 * HD + lane * 4];
        acc.x += (a.x + b.x) + (c.x + d.x) + (ee.x + f.x) + (g.x + hh.x);
        acc.y += (a.y + b.y) + (c.y + d.y) + (ee.y + f.y) + (g.y + hh.y);
        acc.z += (a.z + b.z) + (c.z + d.z) + (ee.z + f.z) + (g.z + hh.z);
        acc.w += (a.w + b.w) + (c.w + d.w) + (ee.w + f.w) + (g.w + hh.w);
    }
    for (; p + 4 <= end; p += 4) {
        int e0 = g_adj_v[p], e1 = g_adj_v[p + 1], e2 = g_adj_v[p + 2], e3 = g_adj_v[p + 3];
        float4 a = *(const float4*)&g_Xe[e0 * HD + lane * 4];
        float4 b = *(const float4*)&g_Xe[e1 * HD + lane * 4];
        float4 c = *(const float4*)&g_Xe[e2 * HD + lane * 4];
        float4 d = *(const float4*)&g_Xe[e3 * HD + lane * 4];
        acc.x += (a.x + b.x) + (c.x + d.x);
        acc.y += (a.y + b.y) + (c.y + d.y);
        acc.z += (a.z + b.z) + (c.z + d.z);
        acc.w += (a.w + b.w) + (c.w + d.w);
    }
    for (; p < end; p++) {
        int e = g_adj_v[p];
        float4 a = *(const float4*)&g_Xe[e * HD + lane * 4];
        acc.x += a.x; acc.y += a.y; acc.z += a.z; acc.w += a.w;
    }
    float ss = acc.x * acc.x + acc.y * acc.y + acc.z * acc.z + acc.w * acc.w;
    #pragma unroll
    for (int o = 16; o > 0; o >>= 1) ss += __shfl_xor_sync(0xffffffffu, ss, o);
    float s9 = (ss > 0.f) ? (0.9f / sqrtf(ss)) : 0.f;
    float4 x0 = *(const float4*)&g_h0[v * HD + lane * 4];
    float4 o;
    o.x = acc.x * s9 + 0.1f * x0.x;
    o.y = acc.y * s9 + 0.1f * x0.y;
    o.z = acc.z * s9 + 0.1f * x0.z;
    o.w = acc.w * s9 + 0.1f * x0.w;
    // split to bf16 hi/lo pairs; lane owns k = lane*4..+3 -> pairs 2*lane, 2*lane+1
    __nv_bfloat16 h0b, l0b, h1b, l1b, h2b, l2b, h3b, l3b;
    bsplit(o.x, h0b, l0b);
    bsplit(o.y, h1b, l1b);
    bsplit(o.z, h2b, l2b);
    bsplit(o.w, h3b, l3b);
    uint2 uhi, ulo;
    uhi.x = packbf(h0b, h1b); uhi.y = packbf(h2b, h3b);
    ulo.x = packbf(l0b, l1b); ulo.y = packbf(l2b, l3b);
    ((uint2*)g_Xhi)[v * 32 + lane] = uhi;
    ((uint2*)g_Xlo)[v * 32 + lane] = ulo;
}

// ---- MMA GEMM shared pieces --------------------------------------------
#define GB_SMEM (4 * 8192 * 4)

__device__ __forceinline__ void gemm_core_and_epilogue(
    uint32_t* dyn, const float* bias, bool hasBias,
    float* C, float* C2, int m0, int Mrows, int tid)
{
    uint32_t* sAhi = dyn;
    uint32_t* sAlo = dyn + 8192;
    uint32_t* sBhi = dyn + 16384;
    uint32_t* sBlo = dyn + 24576;

    int wid = tid >> 5;
    int lane = tid & 31;
    int mwarp = wid & 3;
    int nwarp = wid >> 2;
    int mt0 = mwarp * 2;
    int nt0 = nwarp * 8;

    float acc[2][8][4];
    #pragma unroll
    for (int i = 0; i < 2; i++)
        #pragma unroll
        for (int j = 0; j < 8; j++)
            #pragma unroll
            for (int q = 0; q < 4; q++) acc[i][j][q] = 0.f;

    #pragma unroll 1
    for (int seg = 0; seg < 3; seg++) {
        const uint4* aBuf = (const uint4*)(seg == 1 ? sAlo : sAhi);
        const uint2* bBuf = (const uint2*)(seg == 2 ? sBlo : sBhi);
        #pragma unroll 1
        for (int kt = 0; kt < 8; kt++) {
            uint4 afr[2];
            afr[0] = aBuf[(kt * 8 + mt0) * 32 + lane];
            afr[1] = aBuf[(kt * 8 + mt0 + 1) * 32 + lane];
            uint2 bfr[8];
            #pragma unroll
            for (int j = 0; j < 8; j++)
                bfr[j] = bBuf[(kt * 16 + nt0 + j) * 32 + lane];
            #pragma unroll
            for (int i = 0; i < 2; i++)
                #pragma unroll
                for (int j = 0; j < 8; j++)
                    mma16816(acc[i][j], afr[i], bfr[j]);
        }
    }

    int rbase = m0 + mwarp * 32 + (lane >> 2);
    int cbase = nwarp * 64 + (lane & 3) * 2;
    #pragma unroll
    for (int i = 0; i < 2; i++) {
        #pragma unroll
        for (int j = 0; j < 8; j++) {
            int col = cbase + j * 8;
            float bx = hasBias ? bias[col] : 0.f;
            float by = hasBias ? bias[col + 1] : 0.f;
            int r0 = rbase + i * 16;
            if (r0 < Mrows) {
                float2 v;
                v.x = fmaxf(acc[i][j][0] + bx, 0.f);
                v.y = fmaxf(acc[i][j][1] + by, 0.f);
                *(float2*)&C[r0 * HD + col] = v;
                if (C2) *(float2*)&C2[r0 * HD + col] = v;
            }
            int r1 = rbase + i * 16 + 8;
            if (r1 < Mrows) {
                float2 v;
                v.x = fmaxf(acc[i][j][2] + bx, 0.f);
                v.y = fmaxf(acc[i][j][3] + by, 0.f);
                *(float2*)&C[r1 * HD + col] = v;
                if (C2) *(float2*)&C2[r1 * HD + col] = v;
            }
        }
    }
}

__device__ __forceinline__ void stage_B(uint32_t* dyn, int slot, int tid) {
    const uint4* srcH = (const uint4*)(g_Bhi + slot * HD * HD);
    const uint4* srcL = (const uint4*)(g_Blo + slot * HD * HD);
    uint4* dstH = (uint4*)(dyn + 16384);
    uint4* dstL = (uint4*)(dyn + 24576);
    #pragma unroll
    for (int it = 0; it < 8; it++) {
        dstH[tid + it * 256] = srcH[tid + it * 256];
        dstL[tid + it * 256] = srcL[tid + it * 256];
    }
}

// ---- layer-0 GEMM: h = h0 = relu(x @ W0 + b0), A from fp32 gmem --------
__global__ __launch_bounds__(256, 1) void gemm_mma0(
    const float* __restrict__ A, const float* __restrict__ bias, int Mrows)
{
    extern __shared__ uint32_t dyn[];
    int tid = threadIdx.x;
    int m0 = blockIdx.x * 128;

    stage_B(dyn, 0, tid);
    {
        uint32_t* sAhi = dyn;
        uint32_t* sAlo = dyn + 8192;
        #pragma unroll
        for (int it = 0; it < 32; it++) {
            int idx2 = tid + it * 256;
            int m = idx2 >> 6;
            int k = (idx2 & 63) * 2;
            int gm = min(m0 + m, Mrows - 1);
            float2 a = *(const float2*)&A[gm * HD + k];
            __nv_bfloat16 h0b, l0b, h1b, l1b;
            bsplit(a.x, h0b, l0b);
            bsplit(a.y, h1b, l1b);
            int kt = k >> 4, kc = k & 15;
            int mt = m >> 4, r = m & 15;
            int lane = (r & 7) * 4 + ((kc & 7) >> 1);
            int reg = (r >> 3) + ((kc >> 3) << 1);
            int w32 = (((kt * 8 + mt) * 32 + lane) << 2) + reg;
            sAhi[w32] = packbf(h0b, h1b);
            sAlo[w32] = packbf(l0b, l1b);
        }
    }
    __syncthreads();
    gemm_core_and_epilogue(dyn, bias, true, g_h, g_h0, m0, Mrows, tid);
}

// ---- layer GEMM: h = relu(Xi @ W'), A pre-split by k_vert_agg ----------
// A-staging is a pure permutation copy. Warp covers 8 rows x 4 q-chunks
// (qq = t&3, mm = t>>2) so STS banks spread: same-row threads collide only
// 2-way; distinct rows map to distinct (r&7)*4 bank groups.
__global__ __launch_bounds__(256, 1) void gemm_layer(int slot, int Mrows)
{
    extern __shared__ uint32_t dyn[];
    int tid = threadIdx.x;
    int m0 = blockIdx.x * 128;

    stage_B(dyn, slot, tid);
    {
        uint32_t* sAhi = dyn;
        uint32_t* sAlo = dyn + 8192;
        int qq = tid & 3;          // uint4 sub-index within 64B
        int mm = tid >> 2;         // 0..63
        #pragma unroll
        for (int it = 0; it < 8; it++) {
            int m = mm + (it & 1) * 64;        // row 0..127
            int q = qq + (it >> 1) * 4;        // uint4 0..15 within row
            int v = min(m0 + m, Mrows - 1);
            uint4 hi4 = ((const uint4*)(g_Xhi + v * 64))[q];
            uint4 lo4 = ((const uint4*)(g_Xlo + v * 64))[q];
            int mt = m >> 4, r = m & 15;
            int kt = q >> 1;                   // k-tile 0..7
            int reg = (r >> 3) + ((q & 1) << 1);
            int base = ((kt * 8 + mt) * 32 + (r & 7) * 4) << 2;
            sAhi[base + reg]      = hi4.x;
            sAhi[base + 4 + reg]  = hi4.y;
            sAhi[base + 8 + reg]  = hi4.z;
            sAhi[base + 12 + reg] = hi4.w;
            sAlo[base + reg]      = lo4.x;
            sAlo[base + 4 + reg]  = lo4.y;
            sAlo[base + 8 + reg]  = lo4.z;
            sAlo[base + 12 + reg] = lo4.w;
        }
    }
    __syncthreads();
    gemm_core_and_epilogue(dyn, nullptr, false, g_h, nullptr, m0, Mrows, tid);
}

// -------- output GEMM: [M,128] @ [128,40] + bias (f32x2 inner) ------------
__global__ __launch_bounds__(320) void gemm_out(
    const float* __restrict__ A, const float* __restrict__ W,
    const float* __restrict__ bias, float* __restrict__ C, int Mrows)
{
    __shared__ float xs[128][33];
    __shared__ float ws[128][40];
    int tid = threadIdx.x;
    int m0 = blockIdx.x * 128;

    for (int idx = tid; idx < 128 * 40; idx += 320)
        ws[idx / 40][idx % 40] = W[idx];

    int slot = tid / 5;
    int cg = tid % 5;
    int r0 = slot, r1 = slot + 64;

    u64 acc[2][4];
    #pragma unroll
    for (int r = 0; r < 2; r++)
        #pragma unroll
        for (int j = 0; j < 4; j++) acc[r][j] = 0ull;

    for (int kc = 0; kc < HD; kc += 32) {
        __syncthreads();
        for (int idx = tid; idx < 128 * 32; idx += 320) {
            int r = idx >> 5, k = idx & 31;
            int m = min(m0 + r, Mrows - 1);
            xs[r][k] = A[m * HD + kc + k];
        }
        __syncthreads();
        #pragma unroll
        for (int k = 0; k < 32; k++) {
            u64 aa0 = bcast2(xs[r0][k]);
            u64 aa1 = bcast2(xs[r1][k]);
            ulonglong2 wp0 = *(const ulonglong2*)&ws[kc + k][cg * 8];
            ulonglong2 wp1 = *(const ulonglong2*)&ws[kc + k][cg * 8 + 4];
            ffma2(acc[0][0], aa0, wp0.x, acc[0][0]);
            ffma2(acc[0][1], aa0, wp0.y, acc[0][1]);
            ffma2(acc[0][2], aa0, wp1.x, acc[0][2]);
            ffma2(acc[0][3], aa0, wp1.y, acc[0][3]);
            ffma2(acc[1][0], aa1, wp0.x, acc[1][0]);
            ffma2(acc[1][1], aa1, wp0.y, acc[1][1]);
            ffma2(acc[1][2], aa1, wp1.x, acc[1][2]);
            ffma2(acc[1][3], aa1, wp1.y, acc[1][3]);
        }
    }

    #pragma unroll
    for (int r = 0; r < 2; r++) {
        int m = m0 + (r ? r1 : r0);
        if (m < Mrows) {
            float v[8];
            #pragma unroll
            for (int j2 = 0; j2 < 4; j2++) {
                float2 f = unpack2(acc[r][j2]);
                v[j2 * 2 + 0] = f.x + bias[cg * 8 + j2 * 2 + 0];
                v[j2 * 2 + 1] = f.y + bias[cg * 8 + j2 * 2 + 1];
            }
            float4* dst = (float4*)&C[m * NCLS + cg * 8];
            dst[0] = *(float4*)&v[0];
            dst[1] = *(float4*)&v[4];
        }
    }
}

// ---------------------------------------------------------------------
extern "C" void kernel_launch(void* const* d_in, const int* in_sizes, int n_in,
                              void* d_out, int out_size) {
    const float* x    = (const float*)d_in[0];
    const float* W0   = (const float*)d_in[1];
    const float* b0   = (const float*)d_in[2];
    const float* Ws   = (const float*)d_in[3];
    const float* Wout = (const float*)d_in[4];
    const float* bout = (const float*)d_in[5];
    const int* vtx    = (const int*)d_in[6];
    const int* edg    = (const int*)d_in[7];
    float* out = (float*)d_out;

    float* h;
    cudaGetSymbolAddress((void**)&h, g_h);

    cudaFuncSetAttribute(gemm_mma0,
                         cudaFuncAttributeMaxDynamicSharedMemorySize, GB_SMEM);
    cudaFuncSetAttribute(gemm_layer,
                         cudaFuncAttributeMaxDynamicSharedMemorySize, GB_SMEM);

    const int gemmBlocks = (NV + 127) / 128;

    // CSR build
    k_zero_counts<<<(ME + NV + 255) / 256, 256>>>();
    k_count<<<(NNZE + 255) / 256, 256>>>(vtx, edg);
    k_scan<<<2, 1024>>>();
    k_fill<<<(NNZE + 255) / 256, 256>>>(vtx, edg);

    // weight prep: all 5 slots in one launch
    k_prep_frag<<<dim3((HD * HD + 255) / 256, 5), 256>>>(W0, Ws);

    // h = h0 = relu(x @ W0 + b0)
    gemm_mma0<<<gemmBlocks, 256, GB_SMEM>>>(x, b0, NV);

    for (int i = 0; i < DEPTH; i++) {
        k_edge_agg<<<(ME * 32 + 255) / 256, 256>>>();
        k_vert_agg<<<(NV * 32 + 255) / 256, 256>>>();
        // h = relu(Xi @ ((1-b)I + b*Ws[i]))
        gemm_layer<<<gemmBlocks, 256, GB_SMEM>>>(i + 1, NV);
    }

    gemm_out<<<gemmBlocks, 320>>>(h, Wout, bout, out, NV);
}

// round 15
// speedup vs baseline: 1.3465x; 1.0508x over previous
#include <cuda_runtime.h>
#include <cuda_bf16.h>
#include <cstdint>
#include <math.h>

#define NV   100000
#define ME   50000
#define NNZE 800000
#define HD   128
#define NCLS 40
#define DEPTH 4

typedef unsigned long long u64;

// -------- scratch (no allocations allowed; __device__ globals) --------
__device__ float g_h [NV * HD];     // current features x
__device__ float g_h0[NV * HD];     // x0 (post first relu)
__device__ float g_Xe[ME * HD];     // edge features
// blended GEMM input, pre-split to bf16 hi/lo, row-major bf16x2 pairs
__device__ __align__(16) uint32_t g_Xhi[NV * 64];
__device__ __align__(16) uint32_t g_Xlo[NV * 64];
// weights pre-split to bf16 hi/lo in MMA fragment layout. slot0=W0, 1..4=folded
__device__ __align__(16) __nv_bfloat16 g_Bhi[5 * HD * HD];
__device__ __align__(16) __nv_bfloat16 g_Blo[5 * HD * HD];
__device__ int g_cnt_e[ME], g_cnt_v[NV];
__device__ int g_off_e[ME + 1], g_off_v[NV + 1];
__device__ int g_cur_e[ME], g_cur_v[NV];
__device__ int g_adj_e[NNZE];   // vertex ids grouped by edge
__device__ int g_adj_v[NNZE];   // edge ids grouped by vertex

// -------- f32x2 helpers (used by gemm_out) -----------------------------
__device__ __forceinline__ void ffma2(u64& d, u64 a, u64 b, u64 c) {
    asm("fma.rn.f32x2 %0, %1, %2, %3;" : "=l"(d) : "l"(a), "l"(b), "l"(c));
}
__device__ __forceinline__ u64 bcast2(float a) {
    u64 r;
    asm("mov.b64 %0, {%1, %1};" : "=l"(r) : "f"(a));
    return r;
}
__device__ __forceinline__ float2 unpack2(u64 u) {
    float2 f;
    asm("mov.b64 {%0, %1}, %2;" : "=f"(f.x), "=f"(f.y) : "l"(u));
    return f;
}

// -------- bf16 split helpers -------------------------------------------
__device__ __forceinline__ void bsplit(float a, __nv_bfloat16& hi, __nv_bfloat16& lo) {
    hi = __float2bfloat16_rn(a);
    lo = __float2bfloat16_rn(a - __bfloat162float(hi));
}
__device__ __forceinline__ uint32_t packbf(__nv_bfloat16 a, __nv_bfloat16 b) {
    __nv_bfloat162 p;
    p.x = a; p.y = b;
    return *(uint32_t*)&p;
}

// mma.sync m16n8k16 bf16 -> f32 accum (baseline PTX, no arch suffix)
__device__ __forceinline__ void mma16816(float* d, const uint4& a, const uint2& b) {
    asm volatile(
        "mma.sync.aligned.m16n8k16.row.col.f32.bf16.bf16.f32 "
        "{%0,%1,%2,%3}, {%4,%5,%6,%7}, {%8,%9}, {%0,%1,%2,%3};"
        : "+f"(d[0]), "+f"(d[1]), "+f"(d[2]), "+f"(d[3])
        : "r"(a.x), "r"(a.y), "r"(a.z), "r"(a.w), "r"(b.x), "r"(b.y));
}

// ---------------------------------------------------------------------
__global__ void k_zero_counts() {
    int i = blockIdx.x * blockDim.x + threadIdx.x;
    if (i < ME) g_cnt_e[i] = 0;
    if (i < NV) g_cnt_v[i] = 0;
}

__global__ void k_count(const int* __restrict__ vtx, const int* __restrict__ edg) {
    int i = blockIdx.x * blockDim.x + threadIdx.x;
    if (i >= NNZE) return;
    atomicAdd(&g_cnt_e[edg[i]], 1);
    atomicAdd(&g_cnt_v[vtx[i]], 1);
}

__global__ void k_scan() {
    const int which = blockIdx.x;
    const int len = which ? NV : ME;
    const int* cnt = which ? g_cnt_v : g_cnt_e;
    int* off = which ? g_off_v : g_off_e;
    int* cur = which ? g_cur_v : g_cur_e;

    __shared__ int sm[1024];
    int t = threadIdx.x;
    int chunk = (len + 1023) >> 10;
    int lo = t * chunk;
    int hi = min(lo + chunk, len);

    int s = 0;
    for (int i = lo; i < hi; i++) s += cnt[i];
    sm[t] = s;
    __syncthreads();
    for (int o = 1; o < 1024; o <<= 1) {
        int add = (t >= o) ? sm[t - o] : 0;
        __syncthreads();
        sm[t] += add;
        __syncthreads();
    }
    int excl = sm[t] - s;
    int run = excl;
    for (int i = lo; i < hi; i++) {
        off[i] = run;
        cur[i] = run;
        run += cnt[i];
    }
    if (t == 1023) off[len] = run;
}

__global__ void k_fill(const int* __restrict__ vtx, const int* __restrict__ edg) {
    int i = blockIdx.x * blockDim.x + threadIdx.x;
    if (i >= NNZE) return;
    int e = edg[i], v = vtx[i];
    int pe = atomicAdd(&g_cur_e[e], 1);
    g_adj_e[pe] = v;
    int pv = atomicAdd(&g_cur_v[v], 1);
    g_adj_v[pv] = e;
}

// -------- weight prep (all 5 slots in one launch, grid.y = slot) --------
__global__ void k_prep_frag(const float* __restrict__ W0, const float* __restrict__ Ws) {
    int slot = blockIdx.y;
    int idx = blockIdx.x * blockDim.x + threadIdx.x;
    if (idx >= HD * HD) return;
    const float* W = (slot == 0) ? W0 : Ws + (slot - 1) * HD * HD;
    int k = idx >> 7, n = idx & 127;
    float w = W[idx];
    if (slot > 0) {
        float beta = logf(0.5f / (float)slot + 1.0f);
        w = beta * w;
        if (k == n) w += (1.0f - beta);
    }
    __nv_bfloat16 hi, lo;
    bsplit(w, hi, lo);
    int kt = k >> 4, kc = k & 15;
    int nt = n >> 3, nc = n & 7;
    int lane = nc * 4 + ((kc & 7) >> 1);
    int elem = ((kt * 16 + nt) * 32 + lane) * 4 + ((kc >> 3) << 1) + (kc & 1);
    g_Bhi[slot * HD * HD + elem] = hi;
    g_Blo[slot * HD * HD + elem] = lo;
}

// -------- edge aggregation: warp per edge, gather-only, MLP-4 -----------
__global__ __launch_bounds__(256) void k_edge_agg() {
    int e = (blockIdx.x * blockDim.x + threadIdx.x) >> 5;
    if (e >= ME) return;
    int lane = threadIdx.x & 31;
    int beg = g_off_e[e], end = g_off_e[e + 1];
    float4 acc = make_float4(0.f, 0.f, 0.f, 0.f);
    int p = beg;
    for (; p + 4 <= end; p += 4) {
        int v0 = g_adj_e[p], v1 = g_adj_e[p + 1], v2 = g_adj_e[p + 2], v3 = g_adj_e[p + 3];
        float4 a = *(const float4*)&g_h[v0 * HD + lane * 4];
        float4 b = *(const float4*)&g_h[v1 * HD + lane * 4];
        float4 c = *(const float4*)&g_h[v2 * HD + lane * 4];
        float4 d = *(const float4*)&g_h[v3 * HD + lane * 4];
        acc.x += (a.x + b.x) + (c.x + d.x);
        acc.y += (a.y + b.y) + (c.y + d.y);
        acc.z += (a.z + b.z) + (c.z + d.z);
        acc.w += (a.w + b.w) + (c.w + d.w);
    }
    for (; p < end; p++) {
        int v = g_adj_e[p];
        float4 a = *(const float4*)&g_h[v * HD + lane * 4];
        acc.x += a.x; acc.y += a.y; acc.z += a.z; acc.w += a.w;
    }
    float inv = 1.0f / (float)max(end - beg, 1);
    acc.x *= inv; acc.y *= inv; acc.z *= inv; acc.w *= inv;
    *(float4*)&g_Xe[e * HD + lane * 4] = acc;
}

// vertex agg (MLP-4) + L2-normalize + alpha blend + bf16 hi/lo split.
// Writes row-major bf16x2 pair arrays; split ALU hides under gather latency.
__global__ __launch_bounds__(256) void k_vert_agg() {
    int v = (blockIdx.x * blockDim.x + threadIdx.x) >> 5;
    if (v >= NV) return;
    int lane = threadIdx.x & 31;
    int beg = g_off_v[v], end = g_off_v[v + 1];
    float4 acc = make_float4(0.f, 0.f, 0.f, 0.f);
    int p = beg;
    for (; p + 4 <= end; p += 4) {
        int e0 = g_adj_v[p], e1 = g_adj_v[p + 1], e2 = g_adj_v[p + 2], e3 = g_adj_v[p + 3];
        float4 a = *(const float4*)&g_Xe[e0 * HD + lane * 4];
        float4 b = *(const float4*)&g_Xe[e1 * HD + lane * 4];
        float4 c = *(const float4*)&g_Xe[e2 * HD + lane * 4];
        float4 d = *(const float4*)&g_Xe[e3 * HD + lane * 4];
        acc.x += (a.x + b.x) + (c.x + d.x);
        acc.y += (a.y + b.y) + (c.y + d.y);
        acc.z += (a.z + b.z) + (c.z + d.z);
        acc.w += (a.w + b.w) + (c.w + d.w);
    }
    for (; p < end; p++) {
        int e = g_adj_v[p];
        float4 a = *(const float4*)&g_Xe[e * HD + lane * 4];
        acc.x += a.x; acc.y += a.y; acc.z += a.z; acc.w += a.w;
    }
    float ss = acc.x * acc.x + acc.y * acc.y + acc.z * acc.z + acc.w * acc.w;
    #pragma unroll
    for (int o = 16; o > 0; o >>= 1) ss += __shfl_xor_sync(0xffffffffu, ss, o);
    float s9 = (ss > 0.f) ? (0.9f / sqrtf(ss)) : 0.f;
    float4 x0 = *(const float4*)&g_h0[v * HD + lane * 4];
    float4 o;
    o.x = acc.x * s9 + 0.1f * x0.x;
    o.y = acc.y * s9 + 0.1f * x0.y;
    o.z = acc.z * s9 + 0.1f * x0.z;
    o.w = acc.w * s9 + 0.1f * x0.w;
    // split to bf16 hi/lo pairs; lane owns k = lane*4..+3 -> pairs 2*lane, 2*lane+1
    __nv_bfloat16 h0b, l0b, h1b, l1b, h2b, l2b, h3b, l3b;
    bsplit(o.x, h0b, l0b);
    bsplit(o.y, h1b, l1b);
    bsplit(o.z, h2b, l2b);
    bsplit(o.w, h3b, l3b);
    uint2 uhi, ulo;
    uhi.x = packbf(h0b, h1b); uhi.y = packbf(h2b, h3b);
    ulo.x = packbf(l0b, l1b); ulo.y = packbf(l2b, l3b);
    ((uint2*)g_Xhi)[v * 32 + lane] = uhi;
    ((uint2*)g_Xlo)[v * 32 + lane] = ulo;
}

// ---- MMA GEMM shared pieces --------------------------------------------
#define GB_SMEM (4 * 8192 * 4)

__device__ __forceinline__ void gemm_core_and_epilogue(
    uint32_t* dyn, const float* bias, bool hasBias,
    float* C, float* C2, int m0, int Mrows, int tid)
{
    uint32_t* sAhi = dyn;
    uint32_t* sAlo = dyn + 8192;
    uint32_t* sBhi = dyn + 16384;
    uint32_t* sBlo = dyn + 24576;

    int wid = tid >> 5;
    int lane = tid & 31;
    int mwarp = wid & 3;
    int nwarp = wid >> 2;
    int mt0 = mwarp * 2;
    int nt0 = nwarp * 8;

    float acc[2][8][4];
    #pragma unroll
    for (int i = 0; i < 2; i++)
        #pragma unroll
        for (int j = 0; j < 8; j++)
            #pragma unroll
            for (int q = 0; q < 4; q++) acc[i][j][q] = 0.f;

    #pragma unroll 1
    for (int seg = 0; seg < 3; seg++) {
        const uint4* aBuf = (const uint4*)(seg == 1 ? sAlo : sAhi);
        const uint2* bBuf = (const uint2*)(seg == 2 ? sBlo : sBhi);
        #pragma unroll 1
        for (int kt = 0; kt < 8; kt++) {
            uint4 afr[2];
            afr[0] = aBuf[(kt * 8 + mt0) * 32 + lane];
            afr[1] = aBuf[(kt * 8 + mt0 + 1) * 32 + lane];
            uint2 bfr[8];
            #pragma unroll
            for (int j = 0; j < 8; j++)
                bfr[j] = bBuf[(kt * 16 + nt0 + j) * 32 + lane];
            #pragma unroll
            for (int i = 0; i < 2; i++)
                #pragma unroll
                for (int j = 0; j < 8; j++)
                    mma16816(acc[i][j], afr[i], bfr[j]);
        }
    }

    int rbase = m0 + mwarp * 32 + (lane >> 2);
    int cbase = nwarp * 64 + (lane & 3) * 2;
    #pragma unroll
    for (int i = 0; i < 2; i++) {
        #pragma unroll
        for (int j = 0; j < 8; j++) {
            int col = cbase + j * 8;
            float bx = hasBias ? bias[col] : 0.f;
            float by = hasBias ? bias[col + 1] : 0.f;
            int r0 = rbase + i * 16;
            if (r0 < Mrows) {
                float2 v;
                v.x = fmaxf(acc[i][j][0] + bx, 0.f);
                v.y = fmaxf(acc[i][j][1] + by, 0.f);
                *(float2*)&C[r0 * HD + col] = v;
                if (C2) *(float2*)&C2[r0 * HD + col] = v;
            }
            int r1 = rbase + i * 16 + 8;
            if (r1 < Mrows) {
                float2 v;
                v.x = fmaxf(acc[i][j][2] + bx, 0.f);
                v.y = fmaxf(acc[i][j][3] + by, 0.f);
                *(float2*)&C[r1 * HD + col] = v;
                if (C2) *(float2*)&C2[r1 * HD + col] = v;
            }
        }
    }
}

__device__ __forceinline__ void stage_B(uint32_t* dyn, int slot, int tid) {
    const uint4* srcH = (const uint4*)(g_Bhi + slot * HD * HD);
    const uint4* srcL = (const uint4*)(g_Blo + slot * HD * HD);
    uint4* dstH = (uint4*)(dyn + 16384);
    uint4* dstL = (uint4*)(dyn + 24576);
    #pragma unroll
    for (int it = 0; it < 8; it++) {
        dstH[tid + it * 256] = srcH[tid + it * 256];
        dstL[tid + it * 256] = srcL[tid + it * 256];
    }
}

// ---- layer-0 GEMM: h = h0 = relu(x @ W0 + b0), A from fp32 gmem --------
__global__ __launch_bounds__(256, 1) void gemm_mma0(
    const float* __restrict__ A, const float* __restrict__ bias, int Mrows)
{
    extern __shared__ uint32_t dyn[];
    int tid = threadIdx.x;
    int m0 = blockIdx.x * 128;

    stage_B(dyn, 0, tid);
    {
        uint32_t* sAhi = dyn;
        uint32_t* sAlo = dyn + 8192;
        #pragma unroll
        for (int it = 0; it < 32; it++) {
            int idx2 = tid + it * 256;
            int m = idx2 >> 6;
            int k = (idx2 & 63) * 2;
            int gm = min(m0 + m, Mrows - 1);
            float2 a = *(const float2*)&A[gm * HD + k];
            __nv_bfloat16 h0b, l0b, h1b, l1b;
            bsplit(a.x, h0b, l0b);
            bsplit(a.y, h1b, l1b);
            int kt = k >> 4, kc = k & 15;
            int mt = m >> 4, r = m & 15;
            int lane = (r & 7) * 4 + ((kc & 7) >> 1);
            int reg = (r >> 3) + ((kc >> 3) << 1);
            int w32 = (((kt * 8 + mt) * 32 + lane) << 2) + reg;
            sAhi[w32] = packbf(h0b, h1b);
            sAlo[w32] = packbf(l0b, l1b);
        }
    }
    __syncthreads();
    gemm_core_and_epilogue(dyn, bias, true, g_h, g_h0, m0, Mrows, tid);
}

// ---- layer GEMM: h = relu(Xi @ W'), A pre-split by k_vert_agg ----------
// A-staging is a pure permutation copy (conflict-free enumeration).
__global__ __launch_bounds__(256, 1) void gemm_layer(int slot, int Mrows)
{
    extern __shared__ uint32_t dyn[];
    int tid = threadIdx.x;
    int m0 = blockIdx.x * 128;

    stage_B(dyn, slot, tid);
    {
        uint32_t* sAhi = dyn;
        uint32_t* sAlo = dyn + 8192;
        int qq = tid & 3;          // uint4 sub-index within 64B
        int mm = tid >> 2;         // 0..63
        #pragma unroll
        for (int it = 0; it < 8; it++) {
            int m = mm + (it & 1) * 64;        // row 0..127
            int q = qq + (it >> 1) * 4;        // uint4 0..15 within row
            int v = min(m0 + m, Mrows - 1);
            uint4 hi4 = ((const uint4*)(g_Xhi + v * 64))[q];
            uint4 lo4 = ((const uint4*)(g_Xlo + v * 64))[q];
            int mt = m >> 4, r = m & 15;
            int kt = q >> 1;                   // k-tile 0..7
            int reg = (r >> 3) + ((q & 1) << 1);
            int base = ((kt * 8 + mt) * 32 + (r & 7) * 4) << 2;
            sAhi[base + reg]      = hi4.x;
            sAhi[base + 4 + reg]  = hi4.y;
            sAhi[base + 8 + reg]  = hi4.z;
            sAhi[base + 12 + reg] = hi4.w;
            sAlo[base + reg]      = lo4.x;
            sAlo[base + 4 + reg]  = lo4.y;
            sAlo[base + 8 + reg]  = lo4.z;
            sAlo[base + 12 + reg] = lo4.w;
        }
    }
    __syncthreads();
    gemm_core_and_epilogue(dyn, nullptr, false, g_h, nullptr, m0, Mrows, tid);
}

// -------- output GEMM: [M,128] @ [128,40] + bias (f32x2 inner) ------------
__global__ __launch_bounds__(320) void gemm_out(
    const float* __restrict__ A, const float* __restrict__ W,
    const float* __restrict__ bias, float* __restrict__ C, int Mrows)
{
    __shared__ float xs[128][33];
    __shared__ float ws[128][40];
    int tid = threadIdx.x;
    int m0 = blockIdx.x * 128;

    for (int idx = tid; idx < 128 * 40; idx += 320)
        ws[idx / 40][idx % 40] = W[idx];

    int slot = tid / 5;
    int cg = tid % 5;
    int r0 = slot, r1 = slot + 64;

    u64 acc[2][4];
    #pragma unroll
    for (int r = 0; r < 2; r++)
        #pragma unroll
        for (int j = 0; j < 4; j++) acc[r][j] = 0ull;

    for (int kc = 0; kc < HD; kc += 32) {
        __syncthreads();
        for (int idx = tid; idx < 128 * 32; idx += 320) {
            int r = idx >> 5, k = idx & 31;
            int m = min(m0 + r, Mrows - 1);
            xs[r][k] = A[m * HD + kc + k];
        }
        __syncthreads();
        #pragma unroll
        for (int k = 0; k < 32; k++) {
            u64 aa0 = bcast2(xs[r0][k]);
            u64 aa1 = bcast2(xs[r1][k]);
            ulonglong2 wp0 = *(const ulonglong2*)&ws[kc + k][cg * 8];
            ulonglong2 wp1 = *(const ulonglong2*)&ws[kc + k][cg * 8 + 4];
            ffma2(acc[0][0], aa0, wp0.x, acc[0][0]);
            ffma2(acc[0][1], aa0, wp0.y, acc[0][1]);
            ffma2(acc[0][2], aa0, wp1.x, acc[0][2]);
            ffma2(acc[0][3], aa0, wp1.y, acc[0][3]);
            ffma2(acc[1][0], aa1, wp0.x, acc[1][0]);
            ffma2(acc[1][1], aa1, wp0.y, acc[1][1]);
            ffma2(acc[1][2], aa1, wp1.x, acc[1][2]);
            ffma2(acc[1][3], aa1, wp1.y, acc[1][3]);
        }
    }

    #pragma unroll
    for (int r = 0; r < 2; r++) {
        int m = m0 + (r ? r1 : r0);
        if (m < Mrows) {
            float v[8];
            #pragma unroll
            for (int j2 = 0; j2 < 4; j2++) {
                float2 f = unpack2(acc[r][j2]);
                v[j2 * 2 + 0] = f.x + bias[cg * 8 + j2 * 2 + 0];
                v[j2 * 2 + 1] = f.y + bias[cg * 8 + j2 * 2 + 1];
            }
            float4* dst = (float4*)&C[m * NCLS + cg * 8];
            dst[0] = *(float4*)&v[0];
            dst[1] = *(float4*)&v[4];
        }
    }
}

// ---------------------------------------------------------------------
extern "C" void kernel_launch(void* const* d_in, const int* in_sizes, int n_in,
                              void* d_out, int out_size) {
    const float* x    = (const float*)d_in[0];
    const float* W0   = (const float*)d_in[1];
    const float* b0   = (const float*)d_in[2];
    const float* Ws   = (const float*)d_in[3];
    const float* Wout = (const float*)d_in[4];
    const float* bout = (const float*)d_in[5];
    const int* vtx    = (const int*)d_in[6];
    const int* edg    = (const int*)d_in[7];
    float* out = (float*)d_out;

    float* h;
    cudaGetSymbolAddress((void**)&h, g_h);

    cudaFuncSetAttribute(gemm_mma0,
                         cudaFuncAttributeMaxDynamicSharedMemorySize, GB_SMEM);
    cudaFuncSetAttribute(gemm_layer,
                         cudaFuncAttributeMaxDynamicSharedMemorySize, GB_SMEM);

    const int gemmBlocks = (NV + 127) / 128;

    // CSR build
    k_zero_counts<<<(ME + NV + 255) / 256, 256>>>();
    k_count<<<(NNZE + 255) / 256, 256>>>(vtx, edg);
    k_scan<<<2, 1024>>>();
    k_fill<<<(NNZE + 255) / 256, 256>>>(vtx, edg);

    // weight prep: all 5 slots in one launch
    k_prep_frag<<<dim3((HD * HD + 255) / 256, 5), 256>>>(W0, Ws);

    // h = h0 = relu(x @ W0 + b0)
    gemm_mma0<<<gemmBlocks, 256, GB_SMEM>>>(x, b0, NV);

    for (int i = 0; i < DEPTH; i++) {
        k_edge_agg<<<(ME * 32 + 255) / 256, 256>>>();
        k_vert_agg<<<(NV * 32 + 255) / 256, 256>>>();
        // h = relu(Xi @ ((1-b)I + b*Ws[i]))
        gemm_layer<<<gemmBlocks, 256, GB_SMEM>>>(i + 1, NV);
    }

    gemm_out<<<gemmBlocks, 320>>>(h, Wout, bout, out, NV);
}

// round 16
// speedup vs baseline: 1.3945x; 1.0357x over previous
#include <cuda_runtime.h>
#include <cuda_bf16.h>
#include <cstdint>
#include <math.h>

#define NV   100000
#define ME   50000
#define NNZE 800000
#define HD   128
#define NCLS 40
#define DEPTH 4

typedef unsigned long long u64;

// -------- scratch (no allocations allowed; __device__ globals) --------
__device__ float g_h [NV * HD];     // current features x
__device__ float g_h0[NV * HD];     // x0 (post first relu)
__device__ float g_Xi[NV * HD];     // blended GEMM input
__device__ float g_Xe[ME * HD];     // edge features
// weights pre-split to bf16 hi/lo in MMA fragment layout. slot0=W0, 1..4=folded
__device__ __align__(16) __nv_bfloat16 g_Bhi[5 * HD * HD];
__device__ __align__(16) __nv_bfloat16 g_Blo[5 * HD * HD];
__device__ int g_cnt_e[ME], g_cnt_v[NV];
__device__ int g_off_e[ME + 1], g_off_v[NV + 1];
__device__ int g_cur_e[ME], g_cur_v[NV];
__device__ int g_adj_e[NNZE];   // vertex ids grouped by edge
__device__ int g_adj_v[NNZE];   // edge ids grouped by vertex

// -------- f32x2 helpers (used by gemm_out) -----------------------------
__device__ __forceinline__ void ffma2(u64& d, u64 a, u64 b, u64 c) {
    asm("fma.rn.f32x2 %0, %1, %2, %3;" : "=l"(d) : "l"(a), "l"(b), "l"(c));
}
__device__ __forceinline__ u64 bcast2(float a) {
    u64 r;
    asm("mov.b64 %0, {%1, %1};" : "=l"(r) : "f"(a));
    return r;
}
__device__ __forceinline__ float2 unpack2(u64 u) {
    float2 f;
    asm("mov.b64 {%0, %1}, %2;" : "=f"(f.x), "=f"(f.y) : "l"(u));
    return f;
}

// -------- bf16 split helpers -------------------------------------------
__device__ __forceinline__ void bsplit(float a, __nv_bfloat16& hi, __nv_bfloat16& lo) {
    hi = __float2bfloat16_rn(a);
    lo = __float2bfloat16_rn(a - __bfloat162float(hi));
}
__device__ __forceinline__ uint32_t packbf(__nv_bfloat16 a, __nv_bfloat16 b) {
    __nv_bfloat162 p;
    p.x = a; p.y = b;
    return *(uint32_t*)&p;
}

// mma.sync m16n8k16 bf16 -> f32 accum (baseline PTX, no arch suffix)
__device__ __forceinline__ void mma16816(float* d, const uint4& a, const uint2& b) {
    asm volatile(
        "mma.sync.aligned.m16n8k16.row.col.f32.bf16.bf16.f32 "
        "{%0,%1,%2,%3}, {%4,%5,%6,%7}, {%8,%9}, {%0,%1,%2,%3};"
        : "+f"(d[0]), "+f"(d[1]), "+f"(d[2]), "+f"(d[3])
        : "r"(a.x), "r"(a.y), "r"(a.z), "r"(a.w), "r"(b.x), "r"(b.y));
}

// ---------------------------------------------------------------------
__global__ void k_zero_counts() {
    int i = blockIdx.x * blockDim.x + threadIdx.x;
    if (i < ME) g_cnt_e[i] = 0;
    if (i < NV) g_cnt_v[i] = 0;
}

__global__ void k_count(const int* __restrict__ vtx, const int* __restrict__ edg) {
    int i = blockIdx.x * blockDim.x + threadIdx.x;
    if (i >= NNZE) return;
    atomicAdd(&g_cnt_e[edg[i]], 1);
    atomicAdd(&g_cnt_v[vtx[i]], 1);
}

__global__ void k_scan() {
    const int which = blockIdx.x;
    const int len = which ? NV : ME;
    const int* cnt = which ? g_cnt_v : g_cnt_e;
    int* off = which ? g_off_v : g_off_e;
    int* cur = which ? g_cur_v : g_cur_e;

    __shared__ int sm[1024];
    int t = threadIdx.x;
    int chunk = (len + 1023) >> 10;
    int lo = t * chunk;
    int hi = min(lo + chunk, len);

    int s = 0;
    for (int i = lo; i < hi; i++) s += cnt[i];
    sm[t] = s;
    __syncthreads();
    for (int o = 1; o < 1024; o <<= 1) {
        int add = (t >= o) ? sm[t - o] : 0;
        __syncthreads();
        sm[t] += add;
        __syncthreads();
    }
    int excl = sm[t] - s;
    int run = excl;
    for (int i = lo; i < hi; i++) {
        off[i] = run;
        cur[i] = run;
        run += cnt[i];
    }
    if (t == 1023) off[len] = run;
}

__global__ void k_fill(const int* __restrict__ vtx, const int* __restrict__ edg) {
    int i = blockIdx.x * blockDim.x + threadIdx.x;
    if (i >= NNZE) return;
    int e = edg[i], v = vtx[i];
    int pe = atomicAdd(&g_cur_e[e], 1);
    g_adj_e[pe] = v;
    int pv = atomicAdd(&g_cur_v[v], 1);
    g_adj_v[pv] = e;
}

// -------- weight prep (all 5 slots in one launch, grid.y = slot) --------
// B frag (m16n8k16 col operand): (k,n) of 16x8 tile ->
//   lane=(n&7)*4+((k&7)>>1), elem=((kt*16+nt)*32+lane)*4 + ((k>>3)&1)*2 + (k&1)
__global__ void k_prep_frag(const float* __restrict__ W0, const float* __restrict__ Ws) {
    int slot = blockIdx.y;
    int idx = blockIdx.x * blockDim.x + threadIdx.x;
    if (idx >= HD * HD) return;
    const float* W = (slot == 0) ? W0 : Ws + (slot - 1) * HD * HD;
    int k = idx >> 7, n = idx & 127;
    float w = W[idx];
    if (slot > 0) {
        float beta = logf(0.5f / (float)slot + 1.0f);
        w = beta * w;
        if (k == n) w += (1.0f - beta);
    }
    __nv_bfloat16 hi, lo;
    bsplit(w, hi, lo);
    int kt = k >> 4, kc = k & 15;
    int nt = n >> 3, nc = n & 7;
    int lane = nc * 4 + ((kc & 7) >> 1);
    int elem = ((kt * 16 + nt) * 32 + lane) * 4 + ((kc >> 3) << 1) + (kc & 1);
    g_Bhi[slot * HD * HD + elem] = hi;
    g_Blo[slot * HD * HD + elem] = lo;
}

// -------- aggregation: warp per segment, gather-only (fp32, MLP-4) ------
__global__ __launch_bounds__(256) void k_edge_agg() {
    int e = (blockIdx.x * blockDim.x + threadIdx.x) >> 5;
    if (e >= ME) return;
    int lane = threadIdx.x & 31;
    int beg = g_off_e[e], end = g_off_e[e + 1];
    float4 acc = make_float4(0.f, 0.f, 0.f, 0.f);
    int p = beg;
    for (; p + 4 <= end; p += 4) {
        int v0 = g_adj_e[p], v1 = g_adj_e[p + 1], v2 = g_adj_e[p + 2], v3 = g_adj_e[p + 3];
        float4 a = *(const float4*)&g_h[v0 * HD + lane * 4];
        float4 b = *(const float4*)&g_h[v1 * HD + lane * 4];
        float4 c = *(const float4*)&g_h[v2 * HD + lane * 4];
        float4 d = *(const float4*)&g_h[v3 * HD + lane * 4];
        acc.x += (a.x + b.x) + (c.x + d.x);
        acc.y += (a.y + b.y) + (c.y + d.y);
        acc.z += (a.z + b.z) + (c.z + d.z);
        acc.w += (a.w + b.w) + (c.w + d.w);
    }
    for (; p < end; p++) {
        int v = g_adj_e[p];
        float4 a = *(const float4*)&g_h[v * HD + lane * 4];
        acc.x += a.x; acc.y += a.y; acc.z += a.z; acc.w += a.w;
    }
    float inv = 1.0f / (float)max(end - beg, 1);
    acc.x *= inv; acc.y *= inv; acc.z *= inv; acc.w *= inv;
    *(float4*)&g_Xe[e * HD + lane * 4] = acc;
}

// vertex agg fused with L2-normalize + alpha blend.
// division by cnt_v cancels under L2 normalization.
__global__ __launch_bounds__(256) void k_vert_agg() {
    int v = (blockIdx.x * blockDim.x + threadIdx.x) >> 5;
    if (v >= NV) return;
    int lane = threadIdx.x & 31;
    int beg = g_off_v[v], end = g_off_v[v + 1];
    float4 acc = make_float4(0.f, 0.f, 0.f, 0.f);
    int p = beg;
    for (; p + 4 <= end; p += 4) {
        int e0 = g_adj_v[p], e1 = g_adj_v[p + 1], e2 = g_adj_v[p + 2], e3 = g_adj_v[p + 3];
        float4 a = *(const float4*)&g_Xe[e0 * HD + lane * 4];
        float4 b = *(const float4*)&g_Xe[e1 * HD + lane * 4];
        float4 c = *(const float4*)&g_Xe[e2 * HD + lane * 4];
        float4 d = *(const float4*)&g_Xe[e3 * HD + lane * 4];
        acc.x += (a.x + b.x) + (c.x + d.x);
        acc.y += (a.y + b.y) + (c.y + d.y);
        acc.z += (a.z + b.z) + (c.z + d.z);
        acc.w += (a.w + b.w) + (c.w + d.w);
    }
    for (; p < end; p++) {
        int e = g_adj_v[p];
        float4 a = *(const float4*)&g_Xe[e * HD + lane * 4];
        acc.x += a.x; acc.y += a.y; acc.z += a.z; acc.w += a.w;
    }
    float ss = acc.x * acc.x + acc.y * acc.y + acc.z * acc.z + acc.w * acc.w;
    #pragma unroll
    for (int o = 16; o > 0; o >>= 1) ss += __shfl_xor_sync(0xffffffffu, ss, o);
    float s9 = (ss > 0.f) ? (0.9f / sqrtf(ss)) : 0.f;
    float4 x0 = *(const float4*)&g_h0[v * HD + lane * 4];
    float4 o;
    o.x = acc.x * s9 + 0.1f * x0.x;
    o.y = acc.y * s9 + 0.1f * x0.y;
    o.z = acc.z * s9 + 0.1f * x0.z;
    o.w = acc.w * s9 + 0.1f * x0.w;
    *(float4*)&g_Xi[v * HD + lane * 4] = o;
}

// ---- MMA GEMM: C[M,128] = relu(A[M,128] @ W[128,128] (+bias)) ----------
// bf16 2-term split, 3 products: Ahi*Bhi + Alo*Bhi + Ahi*Blo.
// R8 structure: one K=128 pass, 128KB smem, launch_bounds(256,1).
#define GB_SMEM (4 * 8192 * 4)

template <bool BIAS, bool DUAL>
__global__ __launch_bounds__(256, 1) void gemm_mma(
    const float* __restrict__ A, int slot, const float* __restrict__ bias,
    float* __restrict__ C, float* __restrict__ C2, int Mrows)
{
    extern __shared__ uint32_t dyn[];
    uint32_t* sAhi = dyn;
    uint32_t* sAlo = dyn + 8192;
    uint32_t* sBhi = dyn + 16384;
    uint32_t* sBlo = dyn + 24576;

    int tid = threadIdx.x;
    int m0 = blockIdx.x * 128;

    // stage B: straight copy of pre-split frag-layout weights
    {
        const uint4* srcH = (const uint4*)(g_Bhi + slot * HD * HD);
        const uint4* srcL = (const uint4*)(g_Blo + slot * HD * HD);
        uint4* dstH = (uint4*)sBhi;
        uint4* dstL = (uint4*)sBlo;
        #pragma unroll
        for (int it = 0; it < 8; it++) {
            dstH[tid + it * 256] = srcH[tid + it * 256];
            dstL[tid + it * 256] = srcL[tid + it * 256];
        }
    }
    // stage A: coalesced fp32 read, split, frag-layout bf16 write
    {
        #pragma unroll
        for (int it = 0; it < 32; it++) {
            int idx2 = tid + it * 256;            // float2 index
            int m = idx2 >> 6;                    // 0..127
            int k = (idx2 & 63) * 2;              // even k
            int gm = min(m0 + m, Mrows - 1);
            float2 a = *(const float2*)&A[gm * HD + k];
            __nv_bfloat16 h0b, l0b, h1b, l1b;
            bsplit(a.x, h0b, l0b);
            bsplit(a.y, h1b, l1b);
            int kt = k >> 4, kc = k & 15;
            int mt = m >> 4, r = m & 15;
            int lane = (r & 7) * 4 + ((kc & 7) >> 1);
            int reg = (r >> 3) + ((kc >> 3) << 1);
            int w32 = (((kt * 8 + mt) * 32 + lane) << 2) + reg;
            sAhi[w32] = packbf(h0b, h1b);
            sAlo[w32] = packbf(l0b, l1b);
        }
    }
    __syncthreads();

    // warp tiles: 4x2 grid of 32(M) x 64(N)
    int wid = tid >> 5;
    int lane = tid & 31;
    int mwarp = wid & 3;
    int nwarp = wid >> 2;
    int mt0 = mwarp * 2;
    int nt0 = nwarp * 8;

    float acc[2][8][4];
    #pragma unroll
    for (int i = 0; i < 2; i++)
        #pragma unroll
        for (int j = 0; j < 8; j++)
            #pragma unroll
            for (int q = 0; q < 4; q++) acc[i][j][q] = 0.f;

    #pragma unroll 1
    for (int seg = 0; seg < 3; seg++) {
        const uint4* aBuf = (const uint4*)(seg == 1 ? sAlo : sAhi);
        const uint2* bBuf = (const uint2*)(seg == 2 ? sBlo : sBhi);
        #pragma unroll 1
        for (int kt = 0; kt < 8; kt++) {
            uint4 afr[2];
            afr[0] = aBuf[(kt * 8 + mt0) * 32 + lane];
            afr[1] = aBuf[(kt * 8 + mt0 + 1) * 32 + lane];
            uint2 bfr[8];
            #pragma unroll
            for (int j = 0; j < 8; j++)
                bfr[j] = bBuf[(kt * 16 + nt0 + j) * 32 + lane];
            #pragma unroll
            for (int i = 0; i < 2; i++)
                #pragma unroll
                for (int j = 0; j < 8; j++)
                    mma16816(acc[i][j], afr[i], bfr[j]);
        }
    }

    // epilogue: bias + relu + store (dual)
    int rbase = m0 + mwarp * 32 + (lane >> 2);
    int cbase = nwarp * 64 + (lane & 3) * 2;
    #pragma unroll
    for (int i = 0; i < 2; i++) {
        #pragma unroll
        for (int j = 0; j < 8; j++) {
            int col = cbase + j * 8;
            float bx = BIAS ? bias[col] : 0.f;
            float by = BIAS ? bias[col + 1] : 0.f;
            int r0 = rbase + i * 16;
            if (r0 < Mrows) {
                float2 v;
                v.x = fmaxf(acc[i][j][0] + bx, 0.f);
                v.y = fmaxf(acc[i][j][1] + by, 0.f);
                *(float2*)&C[r0 * HD + col] = v;
                if (DUAL) *(float2*)&C2[r0 * HD + col] = v;
            }
            int r1 = rbase + i * 16 + 8;
            if (r1 < Mrows) {
                float2 v;
                v.x = fmaxf(acc[i][j][2] + bx, 0.f);
                v.y = fmaxf(acc[i][j][3] + by, 0.f);
                *(float2*)&C[r1 * HD + col] = v;
                if (DUAL) *(float2*)&C2[r1 * HD + col] = v;
            }
        }
    }
}

// -------- output GEMM: [M,128] @ [128,40] + bias (f32x2 inner) ------------
__global__ __launch_bounds__(320) void gemm_out(
    const float* __restrict__ A, const float* __restrict__ W,
    const float* __restrict__ bias, float* __restrict__ C, int Mrows)
{
    __shared__ float xs[128][33];
    __shared__ float ws[128][40];
    int tid = threadIdx.x;
    int m0 = blockIdx.x * 128;

    for (int idx = tid; idx < 128 * 40; idx += 320)
        ws[idx / 40][idx % 40] = W[idx];

    int slot = tid / 5;
    int cg = tid % 5;
    int r0 = slot, r1 = slot + 64;

    u64 acc[2][4];
    #pragma unroll
    for (int r = 0; r < 2; r++)
        #pragma unroll
        for (int j = 0; j < 4; j++) acc[r][j] = 0ull;

    for (int kc = 0; kc < HD; kc += 32) {
        __syncthreads();
        for (int idx = tid; idx < 128 * 32; idx += 320) {
            int r = idx >> 5, k = idx & 31;
            int m = min(m0 + r, Mrows - 1);
            xs[r][k] = A[m * HD + kc + k];
        }
        __syncthreads();
        #pragma unroll
        for (int k = 0; k < 32; k++) {
            u64 aa0 = bcast2(xs[r0][k]);
            u64 aa1 = bcast2(xs[r1][k]);
            ulonglong2 wp0 = *(const ulonglong2*)&ws[kc + k][cg * 8];
            ulonglong2 wp1 = *(const ulonglong2*)&ws[kc + k][cg * 8 + 4];
            ffma2(acc[0][0], aa0, wp0.x, acc[0][0]);
            ffma2(acc[0][1], aa0, wp0.y, acc[0][1]);
            ffma2(acc[0][2], aa0, wp1.x, acc[0][2]);
            ffma2(acc[0][3], aa0, wp1.y, acc[0][3]);
            ffma2(acc[1][0], aa1, wp0.x, acc[1][0]);
            ffma2(acc[1][1], aa1, wp0.y, acc[1][1]);
            ffma2(acc[1][2], aa1, wp1.x, acc[1][2]);
            ffma2(acc[1][3], aa1, wp1.y, acc[1][3]);
        }
    }

    #pragma unroll
    for (int r = 0; r < 2; r++) {
        int m = m0 + (r ? r1 : r0);
        if (m < Mrows) {
            float v[8];
            #pragma unroll
            for (int j2 = 0; j2 < 4; j2++) {
                float2 f = unpack2(acc[r][j2]);
                v[j2 * 2 + 0] = f.x + bias[cg * 8 + j2 * 2 + 0];
                v[j2 * 2 + 1] = f.y + bias[cg * 8 + j2 * 2 + 1];
            }
            float4* dst = (float4*)&C[m * NCLS + cg * 8];
            dst[0] = *(float4*)&v[0];
            dst[1] = *(float4*)&v[4];
        }
    }
}

// ---------------------------------------------------------------------
extern "C" void kernel_launch(void* const* d_in, const int* in_sizes, int n_in,
                              void* d_out, int out_size) {
    const float* x    = (const float*)d_in[0];
    const float* W0   = (const float*)d_in[1];
    const float* b0   = (const float*)d_in[2];
    const float* Ws   = (const float*)d_in[3];
    const float* Wout = (const float*)d_in[4];
    const float* bout = (const float*)d_in[5];
    const int* vtx    = (const int*)d_in[6];
    const int* edg    = (const int*)d_in[7];
    float* out = (float*)d_out;

    float *h, *h0, *Xi;
    cudaGetSymbolAddress((void**)&h,  g_h);
    cudaGetSymbolAddress((void**)&h0, g_h0);
    cudaGetSymbolAddress((void**)&Xi, g_Xi);

    cudaFuncSetAttribute(gemm_mma<true, true>,
                         cudaFuncAttributeMaxDynamicSharedMemorySize, GB_SMEM);
    cudaFuncSetAttribute(gemm_mma<false, false>,
                         cudaFuncAttributeMaxDynamicSharedMemorySize, GB_SMEM);

    const int gemmBlocks = (NV + 127) / 128;

    // --- fork: CSR build (side stream) ∥ weight prep + first GEMM (main) ---
    // CSR chain depends only on vtx/edg; prep+gemm0 only on x/W0/b0.
    cudaStream_t side = nullptr;
    cudaEvent_t evFork = nullptr, evJoin = nullptr;
    bool forked = (cudaStreamCreateWithFlags(&side, cudaStreamNonBlocking) == cudaSuccess)
               && (cudaEventCreateWithFlags(&evFork, cudaEventDisableTiming) == cudaSuccess)
               && (cudaEventCreateWithFlags(&evJoin, cudaEventDisableTiming) == cudaSuccess);

    cudaStream_t csrS = forked ? side : (cudaStream_t)0;

    if (forked) {
        cudaEventRecord(evFork, 0);
        cudaStreamWaitEvent(side, evFork, 0);
    }

    // CSR build on csrS
    k_zero_counts<<<(ME + NV + 255) / 256, 256, 0, csrS>>>();
    k_count<<<(NNZE + 255) / 256, 256, 0, csrS>>>(vtx, edg);
    k_scan<<<2, 1024, 0, csrS>>>();
    k_fill<<<(NNZE + 255) / 256, 256, 0, csrS>>>(vtx, edg);

    // weight prep + layer-0 GEMM on main stream (concurrent with CSR)
    k_prep_frag<<<dim3((HD * HD + 255) / 256, 5), 256>>>(W0, Ws);
    gemm_mma<true, true><<<gemmBlocks, 256, GB_SMEM>>>(x, 0, b0, h, h0, NV);

    if (forked) {
        cudaEventRecord(evJoin, side);
        cudaStreamWaitEvent(0, evJoin, 0);
    }

    for (int i = 0; i < DEPTH; i++) {
        k_edge_agg<<<(ME * 32 + 255) / 256, 256>>>();
        k_vert_agg<<<(NV * 32 + 255) / 256, 256>>>();
        // h = relu(Xi @ ((1-b)I + b*Ws[i]))
        gemm_mma<false, false><<<gemmBlocks, 256, GB_SMEM>>>(Xi, i + 1, nullptr,
                                                            h, nullptr, NV);
    }

    gemm_out<<<gemmBlocks, 320>>>(h, Wout, bout, out, NV);
}